// round 1
// baseline (speedup 1.0000x reference)
#include <cuda_runtime.h>
#include <cuda_bf16.h>
#include <math.h>

// Problem constants (FlashRWLargeAttention_59064390255025)
#define G_   8
#define H_   16
#define D_   64
#define B_   2
#define S_   1024
#define T_   (B_ * S_)            // 2048
#define HID_ (G_ * H_ * D_)       // 8192
#define NQKV (G_ * (H_ + 2) * D_) // 9216
#define CACHE_SLOTS 4096
#define CACHE_ELEMS (2 * CACHE_SLOTS * G_ * D_) // 4194304
#define OUT_ELEMS ((size_t)T_ * HID_)           // 16777216
#define SCALE_ 0.125f                            // 64^-0.5

// Scratch (allocation-free rule: static __device__ globals)
__device__ float g_qkv[(size_t)T_ * NQKV];        // 75.5 MB
__device__ float g_q  [(size_t)T_ * G_ * H_ * D_]; // 67 MB  rotated Q
__device__ float g_k  [(size_t)T_ * G_ * D_];      // 4 MB   rotated K
__device__ float g_v  [(size_t)T_ * G_ * D_];      // 4 MB
__device__ float g_attn[(size_t)T_ * HID_];        // 67 MB

// ---------------------------------------------------------------------------
// Classic SIMT SGEMM: C[M,N] = A[M,K] @ B[K,N] + bias[N]
// BM=BN=128, BK=8, 256 threads, 8x8 per-thread microtile.
// M,N,K all multiples of tile dims for this problem -> no bounds checks.
// ---------------------------------------------------------------------------
__global__ __launch_bounds__(256) void sgemm_bias(
    const float* __restrict__ A, const float* __restrict__ B,
    const float* __restrict__ bias, float* __restrict__ C,
    int M, int N, int K)
{
    const int BM = 128, BN = 128, BK = 8;
    __shared__ float As[BK][BM];
    __shared__ float Bs[BK][BN];

    int tid  = threadIdx.x;
    int brow = blockIdx.y;
    int bcol = blockIdx.x;

    int tcol = tid & 15;   // 0..15
    int trow = tid >> 4;   // 0..15

    float acc[8][8];
#pragma unroll
    for (int i = 0; i < 8; i++)
#pragma unroll
        for (int j = 0; j < 8; j++) acc[i][j] = 0.f;

    // loader coords
    int aRow = tid >> 1;          // 0..127
    int aCol = (tid & 1) * 4;     // 0 or 4
    int bRow = tid >> 5;          // 0..7
    int bCol = (tid & 31) * 4;    // 0..124

    const float* Ab = A + (size_t)brow * BM * K;
    const float* Bb = B + (size_t)bcol * BN;

    for (int k0 = 0; k0 < K; k0 += BK) {
        float4 a4 = *(const float4*)(Ab + (size_t)aRow * K + k0 + aCol);
        As[aCol + 0][aRow] = a4.x;
        As[aCol + 1][aRow] = a4.y;
        As[aCol + 2][aRow] = a4.z;
        As[aCol + 3][aRow] = a4.w;
        float4 b4 = *(const float4*)(Bb + (size_t)(k0 + bRow) * N + bCol);
        *(float4*)&Bs[bRow][bCol] = b4;
        __syncthreads();

#pragma unroll
        for (int kk = 0; kk < BK; kk++) {
            float ar[8], br[8];
#pragma unroll
            for (int i = 0; i < 8; i++) ar[i] = As[kk][trow * 8 + i];
#pragma unroll
            for (int j = 0; j < 8; j++) br[j] = Bs[kk][tcol * 8 + j];
#pragma unroll
            for (int i = 0; i < 8; i++)
#pragma unroll
                for (int j = 0; j < 8; j++) acc[i][j] += ar[i] * br[j];
        }
        __syncthreads();
    }

#pragma unroll
    for (int i = 0; i < 8; i++) {
        int row = brow * BM + trow * 8 + i;
#pragma unroll
        for (int j = 0; j < 8; j += 4) {
            int col = bcol * BN + tcol * 8 + j;
            float4 o;
            o.x = acc[i][j + 0] + bias[col + 0];
            o.y = acc[i][j + 1] + bias[col + 1];
            o.z = acc[i][j + 2] + bias[col + 2];
            o.w = acc[i][j + 3] + bias[col + 3];
            *(float4*)(C + (size_t)row * N + col) = o;
        }
    }
}

// ---------------------------------------------------------------------------
// Rotary + split: g_qkv -> g_q (rotated), g_k (rotated), g_v
// grid (T, G), 64 threads (one per d)
// ---------------------------------------------------------------------------
__global__ void rotary_split(const float* __restrict__ cosp,
                             const float* __restrict__ sinp)
{
    int t = blockIdx.x;
    int g = blockIdx.y;
    int d = threadIdx.x;
    int half = d & 31;
    float c = cosp[t * 32 + half];
    float s = sinp[t * 32 + half];

    const float* row = g_qkv + (size_t)t * NQKV + (size_t)(g * (H_ + 2)) * D_;

    // Q heads
#pragma unroll 4
    for (int h = 0; h < H_; h++) {
        const float* x = row + h * D_;
        float v0 = x[d];
        float out;
        if (d < 32) { float v1 = x[d + 32]; out = v0 * c - v1 * s; }
        else        { float v1 = x[d - 32]; out = v0 * c + v1 * s; }
        g_q[(((size_t)t * G_ + g) * H_ + h) * D_ + d] = out;
    }
    // K (rotated)
    {
        const float* x = row + H_ * D_;
        float v0 = x[d];
        float out;
        if (d < 32) { float v1 = x[d + 32]; out = v0 * c - v1 * s; }
        else        { float v1 = x[d - 32]; out = v0 * c + v1 * s; }
        g_k[((size_t)t * G_ + g) * D_ + d] = out;
    }
    // V (copy)
    g_v[((size_t)t * G_ + g) * D_ + d] = row[(H_ + 1) * D_ + d];
}

// ---------------------------------------------------------------------------
// Cache: copy input cache into output region, then scatter k/v at slots
// ---------------------------------------------------------------------------
__global__ void cache_copy(const float* __restrict__ src, float* __restrict__ dst)
{
    size_t i = (size_t)blockIdx.x * blockDim.x + threadIdx.x;
    const float4* s4 = (const float4*)src;
    float4* d4 = (float4*)dst;
    size_t n4 = CACHE_ELEMS / 4;
    for (; i < n4; i += (size_t)gridDim.x * blockDim.x) d4[i] = s4[i];
}

__global__ void cache_scatter(const int* __restrict__ slots, float* __restrict__ dst)
{
    int t = blockIdx.x;
    int g = blockIdx.y;
    int d = threadIdx.x;
    int slot = slots[t];
    size_t kidx = ((size_t)slot * G_ + g) * D_ + d;
    dst[kidx] = g_k[((size_t)t * G_ + g) * D_ + d];
    dst[(size_t)CACHE_SLOTS * G_ * D_ + kidx] = g_v[((size_t)t * G_ + g) * D_ + d];
}

// ---------------------------------------------------------------------------
// Flash attention (causal, fp32): one query row per thread, online softmax.
// grid (B*G*H, S/256), 256 threads. KV tiles of 64 in SMEM (broadcast reads).
// ---------------------------------------------------------------------------
__global__ __launch_bounds__(256) void attn_kernel()
{
    int task = blockIdx.x;             // (b*G + g)*H + h
    int h = task % H_;
    int g = (task / H_) % G_;
    int b = task / (H_ * G_);
    int qi = blockIdx.y * 256 + threadIdx.x;   // query position within S
    int t  = b * S_ + qi;

    float q[D_];
    const float* qrow = g_q + (((size_t)t * G_ + g) * H_ + h) * D_;
#pragma unroll
    for (int d = 0; d < D_; d++) q[d] = qrow[d];

    float m = -INFINITY, l = 0.f;
    float acc[D_];
#pragma unroll
    for (int d = 0; d < D_; d++) acc[d] = 0.f;

    __shared__ float Ks[64][D_];
    __shared__ float Vs[64][D_];

    int kv_end = (blockIdx.y + 1) * 256;  // max key+1 needed by this block

    for (int t0 = 0; t0 < kv_end; t0 += 64) {
        __syncthreads();
        for (int i = threadIdx.x; i < 64 * D_; i += 256) {
            int j = i >> 6, d = i & 63;
            size_t src = ((size_t)(b * S_ + t0 + j) * G_ + g) * D_ + d;
            Ks[j][d] = g_k[src];
            Vs[j][d] = g_v[src];
        }
        __syncthreads();

        int jmax = qi - t0 + 1;
        if (jmax > 64) jmax = 64;
        for (int j = 0; j < jmax; j++) {
            float s = 0.f;
#pragma unroll
            for (int d = 0; d < D_; d++) s += q[d] * Ks[j][d];
            s *= SCALE_;
            if (s > m) {
                float corr = __expf(m - s);
                l *= corr;
#pragma unroll
                for (int d = 0; d < D_; d++) acc[d] *= corr;
                m = s;
            }
            float p = __expf(s - m);
            l += p;
#pragma unroll
            for (int d = 0; d < D_; d++) acc[d] += p * Vs[j][d];
        }
    }

    float inv = 1.f / l;
    float* orow = g_attn + (size_t)t * HID_ + (size_t)(g * H_ + h) * D_;
#pragma unroll
    for (int d = 0; d < D_; d++) orow[d] = acc[d] * inv;
}

// ---------------------------------------------------------------------------
// kernel_launch
// Inputs: 0 hidden_states, 1 cos, 2 sin, 3 w_qkv, 4 b_qkv, 5 w_dense,
//         6 b_dense, 7 kv_cache, 8 slots, 9 batch_size
// Output: [ out (T*HID) | new_cache (2*4096*G*D) ]
// ---------------------------------------------------------------------------
extern "C" void kernel_launch(void* const* d_in, const int* in_sizes, int n_in,
                              void* d_out, int out_size)
{
    const float* hidden  = (const float*)d_in[0];
    const float* cosp    = (const float*)d_in[1];
    const float* sinp    = (const float*)d_in[2];
    const float* w_qkv   = (const float*)d_in[3];
    const float* b_qkv   = (const float*)d_in[4];
    const float* w_dense = (const float*)d_in[5];
    const float* b_dense = (const float*)d_in[6];
    const float* kvcache = (const float*)d_in[7];
    const int*   slots   = (const int*)d_in[8];

    float* out       = (float*)d_out;
    float* out_cache = out + OUT_ELEMS;

    float *p_qkv, *p_attn;
    cudaGetSymbolAddress((void**)&p_qkv, g_qkv);
    cudaGetSymbolAddress((void**)&p_attn, g_attn);

    // 1) QKV GEMM: [T, HID] @ [HID, NQKV] + b_qkv
    sgemm_bias<<<dim3(NQKV / 128, T_ / 128), 256>>>(
        hidden, w_qkv, b_qkv, p_qkv, T_, NQKV, HID_);

    // 2) rotary + split into g_q / g_k / g_v
    rotary_split<<<dim3(T_, G_), 64>>>(cosp, sinp);

    // 3) cache: copy then scatter (stream-ordered)
    cache_copy<<<4096, 256>>>(kvcache, out_cache);
    cache_scatter<<<dim3(T_, G_), 64>>>(slots, out_cache);

    // 4) attention -> g_attn
    attn_kernel<<<dim3(B_ * G_ * H_, S_ / 256), 256>>>();

    // 5) dense GEMM: [T, HID] @ [HID, HID] + b_dense -> out
    sgemm_bias<<<dim3(HID_ / 128, T_ / 128), 256>>>(
        p_attn, w_dense, b_dense, out, T_, HID_, HID_);
}

// round 3
// speedup vs baseline: 2.1767x; 2.1767x over previous
#include <cuda_runtime.h>
#include <math.h>
#include <stdint.h>

// Problem constants (FlashRWLargeAttention_59064390255025)
#define G_   8
#define H_   16
#define D_   64
#define B_   2
#define S_   1024
#define T_   (B_ * S_)            // 2048
#define HID_ (G_ * H_ * D_)       // 8192
#define NQKV (G_ * (H_ + 2) * D_) // 9216
#define CACHE_SLOTS 4096
#define CACHE_ELEMS (2 * CACHE_SLOTS * G_ * D_)
#define OUT_ELEMS ((size_t)T_ * HID_)
#define SCALE_ 0.125f

// Scratch (__device__ globals; no allocs allowed)
__device__ float g_qkv [(size_t)T_ * NQKV];
__device__ float g_q   [(size_t)T_ * HID_];
__device__ float g_k   [(size_t)T_ * G_ * D_];
__device__ float g_v   [(size_t)T_ * G_ * D_];
__device__ float g_attn[(size_t)T_ * HID_];

__device__ __forceinline__ uint32_t f2tf32(float x) {
    uint32_t r;
    asm("cvt.rna.tf32.f32 %0, %1;" : "=r"(r) : "f"(x));
    return r;
}

// ---------------------------------------------------------------------------
// tf32 mma.sync GEMM: C[M,N] = A[M,K] @ W[K,N] + bias[N]
// CTA 128x128x32, 8 warps (2m x 4n), warp tile 64x32.
// Double-buffered SMEM + register prefetch. HMMA m16n8k8 tf32.
// ---------------------------------------------------------------------------
#define BM 128
#define BN 128
#define BK 32
#define A_STRIDE 36   // floats per A smem row (pad 128B->144B, 16B aligned)
#define B_STRIDE 132  // floats per B smem row (pad, 16B aligned)
#define A_SZ (BM * A_STRIDE)  // 4608 floats
#define B_SZ (BK * B_STRIDE)  // 4224 floats
#define GEMM_SMEM ((2 * A_SZ + 2 * B_SZ) * 4)  // 70656 bytes

__device__ __forceinline__ void mma_tf32(float* c, const uint32_t* a,
                                         const uint32_t* b) {
    asm volatile(
        "mma.sync.aligned.m16n8k8.row.col.f32.tf32.tf32.f32 "
        "{%0,%1,%2,%3}, {%4,%5,%6,%7}, {%8,%9}, {%0,%1,%2,%3};\n"
        : "+f"(c[0]), "+f"(c[1]), "+f"(c[2]), "+f"(c[3])
        : "r"(a[0]), "r"(a[1]), "r"(a[2]), "r"(a[3]), "r"(b[0]), "r"(b[1]));
}

__global__ __launch_bounds__(256, 2) void gemm_tf32mma(
    const float* __restrict__ A, const float* __restrict__ W,
    const float* __restrict__ bias, float* __restrict__ C,
    int K, int N)
{
    extern __shared__ __align__(16) uint32_t sm[];
    uint32_t* sA[2] = { sm, sm + A_SZ };
    uint32_t* sB[2] = { sm + 2 * A_SZ, sm + 2 * A_SZ + B_SZ };

    const int tid = threadIdx.x;
    const int wid = tid >> 5, lane = tid & 31;
    const int l4r = lane >> 2, l4c = lane & 3;
    const int wm64 = (wid >> 2) * 64;   // warp m offset (0 / 64)
    const int wn32 = (wid & 3) * 32;    // warp n offset (0/32/64/96)
    const int row0 = blockIdx.x * BM;
    const int col0 = blockIdx.y * BN;

    // global loader coords
    const int aRow = tid >> 1;                 // 0..127  (tid*... A: idx>>3)
    (void)aRow;
    // A: 1024 float4, 4 per thread: idx = i*256+tid, row=idx>>3, kq=idx&7
    // B: 1024 float4, 4 per thread: idx = i*256+tid, kr=idx>>5, nq=idx&31

    float acc[4][4][4];
#pragma unroll
    for (int mi = 0; mi < 4; mi++)
#pragma unroll
        for (int ni = 0; ni < 4; ni++)
#pragma unroll
            for (int j = 0; j < 4; j++) acc[mi][ni][j] = 0.f;

    const int NT = K / BK;

    float4 aR[4], bR[4];
    // prologue: load tile 0
#pragma unroll
    for (int i = 0; i < 4; i++) {
        int idx = i * 256 + tid;
        int r = idx >> 3, kq = idx & 7;
        aR[i] = *(const float4*)(A + (size_t)(row0 + r) * K + kq * 4);
        int kr = idx >> 5, nq = idx & 31;
        bR[i] = *(const float4*)(W + (size_t)kr * N + col0 + nq * 4);
    }
#pragma unroll
    for (int i = 0; i < 4; i++) {
        int idx = i * 256 + tid;
        int r = idx >> 3, kq = idx & 7;
        uint4 av = { f2tf32(aR[i].x), f2tf32(aR[i].y), f2tf32(aR[i].z), f2tf32(aR[i].w) };
        *(uint4*)(sA[0] + r * A_STRIDE + kq * 4) = av;
        int kr = idx >> 5, nq = idx & 31;
        uint4 bv = { f2tf32(bR[i].x), f2tf32(bR[i].y), f2tf32(bR[i].z), f2tf32(bR[i].w) };
        *(uint4*)(sB[0] + kr * B_STRIDE + nq * 4) = bv;
    }
    __syncthreads();

    for (int kt = 0; kt < NT; kt++) {
        const int s = kt & 1;
        const bool more = (kt + 1 < NT);
        if (more) {
            const int k0 = (kt + 1) * BK;
#pragma unroll
            for (int i = 0; i < 4; i++) {
                int idx = i * 256 + tid;
                int r = idx >> 3, kq = idx & 7;
                aR[i] = *(const float4*)(A + (size_t)(row0 + r) * K + k0 + kq * 4);
                int kr = idx >> 5, nq = idx & 31;
                bR[i] = *(const float4*)(W + (size_t)(k0 + kr) * N + col0 + nq * 4);
            }
        }

        const uint32_t* As = sA[s];
        const uint32_t* Bs = sB[s];
#pragma unroll
        for (int ks = 0; ks < 4; ks++) {
            const int kk = ks * 8;
            uint32_t af[4][4];
#pragma unroll
            for (int mi = 0; mi < 4; mi++) {
                int r = wm64 + mi * 16 + l4r;
                af[mi][0] = As[r * A_STRIDE + kk + l4c];
                af[mi][1] = As[(r + 8) * A_STRIDE + kk + l4c];
                af[mi][2] = As[r * A_STRIDE + kk + l4c + 4];
                af[mi][3] = As[(r + 8) * A_STRIDE + kk + l4c + 4];
            }
            uint32_t bf[4][2];
#pragma unroll
            for (int ni = 0; ni < 4; ni++) {
                int c = wn32 + ni * 8 + l4r;
                bf[ni][0] = Bs[(kk + l4c) * B_STRIDE + c];
                bf[ni][1] = Bs[(kk + l4c + 4) * B_STRIDE + c];
            }
#pragma unroll
            for (int mi = 0; mi < 4; mi++)
#pragma unroll
                for (int ni = 0; ni < 4; ni++)
                    mma_tf32(acc[mi][ni], af[mi], bf[ni]);
        }

        if (more) {
            uint32_t* Aw = sA[s ^ 1];
            uint32_t* Bw = sB[s ^ 1];
#pragma unroll
            for (int i = 0; i < 4; i++) {
                int idx = i * 256 + tid;
                int r = idx >> 3, kq = idx & 7;
                uint4 av = { f2tf32(aR[i].x), f2tf32(aR[i].y), f2tf32(aR[i].z), f2tf32(aR[i].w) };
                *(uint4*)(Aw + r * A_STRIDE + kq * 4) = av;
                int kr = idx >> 5, nq = idx & 31;
                uint4 bv = { f2tf32(bR[i].x), f2tf32(bR[i].y), f2tf32(bR[i].z), f2tf32(bR[i].w) };
                *(uint4*)(Bw + kr * B_STRIDE + nq * 4) = bv;
            }
        }
        __syncthreads();
    }

    // epilogue: C = acc + bias
#pragma unroll
    for (int mi = 0; mi < 4; mi++) {
        int r = row0 + wm64 + mi * 16 + l4r;
#pragma unroll
        for (int ni = 0; ni < 4; ni++) {
            int c = col0 + wn32 + ni * 8 + l4c * 2;
            float b0 = bias[c], b1 = bias[c + 1];
            float2 v0 = { acc[mi][ni][0] + b0, acc[mi][ni][1] + b1 };
            float2 v1 = { acc[mi][ni][2] + b0, acc[mi][ni][3] + b1 };
            *(float2*)(C + (size_t)r * N + c) = v0;
            *(float2*)(C + (size_t)(r + 8) * N + c) = v1;
        }
    }
}

// ---------------------------------------------------------------------------
// Rotary + split: g_qkv -> g_q (rotated), g_k (rotated), g_v
// ---------------------------------------------------------------------------
__global__ void rotary_split(const float* __restrict__ cosp,
                             const float* __restrict__ sinp)
{
    int t = blockIdx.x;
    int g = blockIdx.y;
    int d = threadIdx.x;
    int half = d & 31;
    float c = cosp[t * 32 + half];
    float s = sinp[t * 32 + half];

    const float* row = g_qkv + (size_t)t * NQKV + (size_t)(g * (H_ + 2)) * D_;

#pragma unroll 4
    for (int h = 0; h < H_; h++) {
        const float* x = row + h * D_;
        float v0 = x[d], out;
        if (d < 32) { float v1 = x[d + 32]; out = v0 * c - v1 * s; }
        else        { float v1 = x[d - 32]; out = v0 * c + v1 * s; }
        g_q[(((size_t)t * G_ + g) * H_ + h) * D_ + d] = out;
    }
    {
        const float* x = row + H_ * D_;
        float v0 = x[d], out;
        if (d < 32) { float v1 = x[d + 32]; out = v0 * c - v1 * s; }
        else        { float v1 = x[d - 32]; out = v0 * c + v1 * s; }
        g_k[((size_t)t * G_ + g) * D_ + d] = out;
    }
    g_v[((size_t)t * G_ + g) * D_ + d] = row[(H_ + 1) * D_ + d];
}

// ---------------------------------------------------------------------------
// Cache copy + scatter
// ---------------------------------------------------------------------------
__global__ void cache_copy(const float* __restrict__ src, float* __restrict__ dst)
{
    size_t i = (size_t)blockIdx.x * blockDim.x + threadIdx.x;
    const float4* s4 = (const float4*)src;
    float4* d4 = (float4*)dst;
    size_t n4 = CACHE_ELEMS / 4;
    for (; i < n4; i += (size_t)gridDim.x * blockDim.x) d4[i] = s4[i];
}

__global__ void cache_scatter(const int* __restrict__ slots, float* __restrict__ dst)
{
    int t = blockIdx.x;
    int g = blockIdx.y;
    int d = threadIdx.x;
    int slot = slots[t];
    size_t kidx = ((size_t)slot * G_ + g) * D_ + d;
    dst[kidx] = g_k[((size_t)t * G_ + g) * D_ + d];
    dst[(size_t)CACHE_SLOTS * G_ * D_ + kidx] = g_v[((size_t)t * G_ + g) * D_ + d];
}

// ---------------------------------------------------------------------------
// Flash attention (causal, fp32): one query row per thread, online softmax.
// ---------------------------------------------------------------------------
__global__ __launch_bounds__(256) void attn_kernel()
{
    int task = blockIdx.x;
    int h = task % H_;
    int g = (task / H_) % G_;
    int b = task / (H_ * G_);
    int qi = blockIdx.y * 256 + threadIdx.x;
    int t  = b * S_ + qi;

    float q[D_];
    const float* qrow = g_q + (((size_t)t * G_ + g) * H_ + h) * D_;
#pragma unroll
    for (int d = 0; d < D_; d++) q[d] = qrow[d];

    float m = -INFINITY, l = 0.f;
    float acc[D_];
#pragma unroll
    for (int d = 0; d < D_; d++) acc[d] = 0.f;

    __shared__ float Ks[64][D_];
    __shared__ float Vs[64][D_];

    int kv_end = (blockIdx.y + 1) * 256;

    for (int t0 = 0; t0 < kv_end; t0 += 64) {
        __syncthreads();
        for (int i = threadIdx.x; i < 64 * D_; i += 256) {
            int j = i >> 6, d = i & 63;
            size_t src = ((size_t)(b * S_ + t0 + j) * G_ + g) * D_ + d;
            Ks[j][d] = g_k[src];
            Vs[j][d] = g_v[src];
        }
        __syncthreads();

        int jmax = qi - t0 + 1;
        if (jmax > 64) jmax = 64;
        for (int j = 0; j < jmax; j++) {
            float s = 0.f;
#pragma unroll
            for (int d = 0; d < D_; d++) s += q[d] * Ks[j][d];
            s *= SCALE_;
            if (s > m) {
                float corr = __expf(m - s);
                l *= corr;
#pragma unroll
                for (int d = 0; d < D_; d++) acc[d] *= corr;
                m = s;
            }
            float p = __expf(s - m);
            l += p;
#pragma unroll
            for (int d = 0; d < D_; d++) acc[d] += p * Vs[j][d];
        }
    }

    float inv = 1.f / l;
    float* orow = g_attn + (size_t)t * HID_ + (size_t)(g * H_ + h) * D_;
#pragma unroll
    for (int d = 0; d < D_; d++) orow[d] = acc[d] * inv;
}

// ---------------------------------------------------------------------------
// kernel_launch
// ---------------------------------------------------------------------------
extern "C" void kernel_launch(void* const* d_in, const int* in_sizes, int n_in,
                              void* d_out, int out_size)
{
    const float* hidden  = (const float*)d_in[0];
    const float* cosp    = (const float*)d_in[1];
    const float* sinp    = (const float*)d_in[2];
    const float* w_qkv   = (const float*)d_in[3];
    const float* b_qkv   = (const float*)d_in[4];
    const float* w_dense = (const float*)d_in[5];
    const float* b_dense = (const float*)d_in[6];
    const float* kvcache = (const float*)d_in[7];
    const int*   slots   = (const int*)d_in[8];

    float* out       = (float*)d_out;
    float* out_cache = out + OUT_ELEMS;

    float *p_qkv, *p_attn;
    cudaGetSymbolAddress((void**)&p_qkv, g_qkv);
    cudaGetSymbolAddress((void**)&p_attn, g_attn);

    cudaFuncSetAttribute(gemm_tf32mma,
        cudaFuncAttributeMaxDynamicSharedMemorySize, GEMM_SMEM);

    // 1) QKV GEMM (tf32 HMMA): [2048,8192] @ [8192,9216] + b_qkv
    gemm_tf32mma<<<dim3(T_ / BM, NQKV / BN), 256, GEMM_SMEM>>>(
        hidden, w_qkv, b_qkv, p_qkv, HID_, NQKV);

    // 2) rotary + split
    rotary_split<<<dim3(T_, G_), 64>>>(cosp, sinp);

    // 3) cache
    cache_copy<<<4096, 256>>>(kvcache, out_cache);
    cache_scatter<<<dim3(T_, G_), 64>>>(slots, out_cache);

    // 4) attention
    attn_kernel<<<dim3(B_ * G_ * H_, S_ / 256), 256>>>();

    // 5) dense GEMM (tf32 HMMA): [2048,8192] @ [8192,8192] + b_dense
    gemm_tf32mma<<<dim3(T_ / BM, HID_ / BN), 256, GEMM_SMEM>>>(
        p_attn, w_dense, b_dense, out, HID_, HID_);
}

// round 4
// speedup vs baseline: 2.2125x; 1.0165x over previous
#include <cuda_runtime.h>
#include <math.h>
#include <stdint.h>

// Problem constants (FlashRWLargeAttention_59064390255025)
#define G_   8
#define H_   16
#define D_   64
#define B_   2
#define S_   1024
#define T_   (B_ * S_)            // 2048
#define HID_ (G_ * H_ * D_)       // 8192
#define NQKV (G_ * (H_ + 2) * D_) // 9216
#define CACHE_SLOTS 4096
#define CACHE_ELEMS (2 * CACHE_SLOTS * G_ * D_)
#define OUT_ELEMS ((size_t)T_ * HID_)
#define SCALE_ 0.125f

typedef unsigned long long u64;

// Scratch (__device__ globals; no allocs allowed)
__device__ float g_qkv [(size_t)T_ * NQKV];
__device__ float g_q   [(size_t)T_ * HID_];
__device__ float g_k   [(size_t)T_ * G_ * D_];
__device__ float g_v   [(size_t)T_ * G_ * D_];
__device__ float g_attn[(size_t)T_ * HID_];

__device__ __forceinline__ uint32_t f2tf32(float x) {
    uint32_t r;
    asm("cvt.rna.tf32.f32 %0, %1;" : "=r"(r) : "f"(x));
    return r;
}
// packed f32x2 helpers (sm_100+ base PTX)
__device__ __forceinline__ u64 fma2(u64 a, u64 b, u64 c) {
    u64 d;
    asm("fma.rn.f32x2 %0, %1, %2, %3;" : "=l"(d) : "l"(a), "l"(b), "l"(c));
    return d;
}
__device__ __forceinline__ u64 add2(u64 a, u64 b) {
    u64 d;
    asm("add.rn.f32x2 %0, %1, %2;" : "=l"(d) : "l"(a), "l"(b));
    return d;
}
__device__ __forceinline__ u64 mul2(u64 a, u64 b) {
    u64 d;
    asm("mul.rn.f32x2 %0, %1, %2;" : "=l"(d) : "l"(a), "l"(b));
    return d;
}
__device__ __forceinline__ u64 pack2(float lo, float hi) {
    u64 r;
    asm("mov.b64 %0, {%1, %2};" : "=l"(r) : "f"(lo), "f"(hi));
    return r;
}
__device__ __forceinline__ void unpack2(u64 v, float& lo, float& hi) {
    asm("mov.b64 {%0, %1}, %2;" : "=f"(lo), "=f"(hi) : "l"(v));
}

// ---------------------------------------------------------------------------
// tf32 mma.sync GEMM v2: C[M,N] = A[M,K] @ W[K,N] + bias[N]
// CTA 128x256x32, 8 warps (2m x 4n), warp tile 64x64.
// Double-buffered SMEM + staged register prefetch. HMMA m16n8k8 tf32.
// ---------------------------------------------------------------------------
#define BM 128
#define BN 256
#define BK 32
#define ASTR 36    // A smem row stride (floats): conflict-free frag reads
#define BSTR 264   // B smem row stride (floats): 264%32==8 -> conflict-free
#define A_SZ (BM * ASTR)   // 4608 floats
#define B_SZ (BK * BSTR)   // 8448 floats
#define GEMM_SMEM ((2 * A_SZ + 2 * B_SZ) * 4)  // 104448 bytes

__device__ __forceinline__ void mma_tf32(float* c, const uint32_t* a,
                                         const uint32_t* b) {
    asm volatile(
        "mma.sync.aligned.m16n8k8.row.col.f32.tf32.tf32.f32 "
        "{%0,%1,%2,%3}, {%4,%5,%6,%7}, {%8,%9}, {%0,%1,%2,%3};\n"
        : "+f"(c[0]), "+f"(c[1]), "+f"(c[2]), "+f"(c[3])
        : "r"(a[0]), "r"(a[1]), "r"(a[2]), "r"(a[3]), "r"(b[0]), "r"(b[1]));
}

__global__ __launch_bounds__(256, 1) void gemm_tf32mma(
    const float* __restrict__ A, const float* __restrict__ W,
    const float* __restrict__ bias, float* __restrict__ C,
    int K, int N)
{
    extern __shared__ __align__(16) uint32_t sm[];
    uint32_t* sA[2] = { sm, sm + A_SZ };
    uint32_t* sB[2] = { sm + 2 * A_SZ, sm + 2 * A_SZ + B_SZ };

    const int tid = threadIdx.x;
    const int wid = tid >> 5, lane = tid & 31;
    const int l4r = lane >> 2, l4c = lane & 3;
    const int wm = (wid >> 2) * 64;    // 0 / 64
    const int wn = (wid & 3) * 64;     // 0/64/128/192
    const int row0 = blockIdx.x * BM;
    const int col0 = blockIdx.y * BN;

    float acc[4][8][4];
#pragma unroll
    for (int mi = 0; mi < 4; mi++)
#pragma unroll
        for (int ni = 0; ni < 8; ni++)
#pragma unroll
            for (int j = 0; j < 4; j++) acc[mi][ni][j] = 0.f;

    const int NT = K / BK;

    // ---- prologue: fill buffer 0 ----
    {
        float4 aR[4];
#pragma unroll
        for (int i = 0; i < 4; i++) {
            int idx = i * 256 + tid;
            int r = idx >> 3, kq = idx & 7;
            aR[i] = *(const float4*)(A + (size_t)(row0 + r) * K + kq * 4);
        }
#pragma unroll
        for (int i = 0; i < 4; i++) {
            int idx = i * 256 + tid;
            int r = idx >> 3, kq = idx & 7;
            uint4 av = { f2tf32(aR[i].x), f2tf32(aR[i].y),
                         f2tf32(aR[i].z), f2tf32(aR[i].w) };
            *(uint4*)(sA[0] + r * ASTR + kq * 4) = av;
        }
#pragma unroll
        for (int half = 0; half < 2; half++) {
            float4 bR[4];
#pragma unroll
            for (int i = 0; i < 4; i++) {
                int idx = (half * 4 + i) * 256 + tid;
                int kr = idx >> 6, nq = idx & 63;
                bR[i] = *(const float4*)(W + (size_t)kr * N + col0 + nq * 4);
            }
#pragma unroll
            for (int i = 0; i < 4; i++) {
                int idx = (half * 4 + i) * 256 + tid;
                int kr = idx >> 6, nq = idx & 63;
                uint4 bv = { f2tf32(bR[i].x), f2tf32(bR[i].y),
                             f2tf32(bR[i].z), f2tf32(bR[i].w) };
                *(uint4*)(sB[0] + kr * BSTR + nq * 4) = bv;
            }
        }
    }
    __syncthreads();

    for (int kt = 0; kt < NT; kt++) {
        const int s = kt & 1;
        const uint32_t* As = sA[s];
        const uint32_t* Bs = sB[s];
        uint32_t* Aw = sA[s ^ 1];
        uint32_t* Bw = sB[s ^ 1];
        const bool more = (kt + 1 < NT);
        const int k0n = (kt + 1) * BK;

        float4 aR[4], bR[4];
        if (more) {
#pragma unroll
            for (int i = 0; i < 4; i++) {
                int idx = i * 256 + tid;
                int r = idx >> 3, kq = idx & 7;
                aR[i] = *(const float4*)(A + (size_t)(row0 + r) * K + k0n + kq * 4);
            }
#pragma unroll
            for (int i = 0; i < 4; i++) {
                int idx = i * 256 + tid;
                int kr = idx >> 6, nq = idx & 63;
                bR[i] = *(const float4*)(W + (size_t)(k0n + kr) * N + col0 + nq * 4);
            }
        }

#pragma unroll
        for (int ks = 0; ks < 4; ks++) {
            const int kk = ks * 8;
            uint32_t af[4][4];
#pragma unroll
            for (int mi = 0; mi < 4; mi++) {
                int r = wm + mi * 16 + l4r;
                af[mi][0] = As[r * ASTR + kk + l4c];
                af[mi][1] = As[(r + 8) * ASTR + kk + l4c];
                af[mi][2] = As[r * ASTR + kk + l4c + 4];
                af[mi][3] = As[(r + 8) * ASTR + kk + l4c + 4];
            }
            uint32_t bf[8][2];
#pragma unroll
            for (int ni = 0; ni < 8; ni++) {
                int c = wn + ni * 8 + l4r;
                bf[ni][0] = Bs[(kk + l4c) * BSTR + c];
                bf[ni][1] = Bs[(kk + l4c + 4) * BSTR + c];
            }
#pragma unroll
            for (int mi = 0; mi < 4; mi++)
#pragma unroll
                for (int ni = 0; ni < 8; ni++)
                    mma_tf32(acc[mi][ni], af[mi], bf[ni]);

            // staged prefetch stores between compute steps
            if (ks == 1 && more) {
#pragma unroll
                for (int i = 0; i < 4; i++) {
                    int idx = i * 256 + tid;
                    int kr = idx >> 6, nq = idx & 63;
                    uint4 bv = { f2tf32(bR[i].x), f2tf32(bR[i].y),
                                 f2tf32(bR[i].z), f2tf32(bR[i].w) };
                    *(uint4*)(Bw + kr * BSTR + nq * 4) = bv;
                }
#pragma unroll
                for (int i = 0; i < 4; i++) {
                    int idx = (4 + i) * 256 + tid;
                    int kr = idx >> 6, nq = idx & 63;
                    bR[i] = *(const float4*)(W + (size_t)(k0n + kr) * N + col0 + nq * 4);
                }
            }
            if (ks == 3 && more) {
#pragma unroll
                for (int i = 0; i < 4; i++) {
                    int idx = i * 256 + tid;
                    int r = idx >> 3, kq = idx & 7;
                    uint4 av = { f2tf32(aR[i].x), f2tf32(aR[i].y),
                                 f2tf32(aR[i].z), f2tf32(aR[i].w) };
                    *(uint4*)(Aw + r * ASTR + kq * 4) = av;
                }
#pragma unroll
                for (int i = 0; i < 4; i++) {
                    int idx = (4 + i) * 256 + tid;
                    int kr = idx >> 6, nq = idx & 63;
                    uint4 bv = { f2tf32(bR[i].x), f2tf32(bR[i].y),
                                 f2tf32(bR[i].z), f2tf32(bR[i].w) };
                    *(uint4*)(Bw + kr * BSTR + nq * 4) = bv;
                }
            }
        }
        __syncthreads();
    }

    // epilogue: C = acc + bias
#pragma unroll
    for (int mi = 0; mi < 4; mi++) {
        int r = row0 + wm + mi * 16 + l4r;
#pragma unroll
        for (int ni = 0; ni < 8; ni++) {
            int c = col0 + wn + ni * 8 + l4c * 2;
            float b0 = bias[c], b1 = bias[c + 1];
            float2 v0 = { acc[mi][ni][0] + b0, acc[mi][ni][1] + b1 };
            float2 v1 = { acc[mi][ni][2] + b0, acc[mi][ni][3] + b1 };
            *(float2*)(C + (size_t)r * N + c) = v0;
            *(float2*)(C + (size_t)(r + 8) * N + c) = v1;
        }
    }
}

// ---------------------------------------------------------------------------
// Rotary + split: g_qkv -> g_q (rotated), g_k (rotated), g_v
// ---------------------------------------------------------------------------
__global__ void rotary_split(const float* __restrict__ cosp,
                             const float* __restrict__ sinp)
{
    int t = blockIdx.x;
    int g = blockIdx.y;
    int d = threadIdx.x;
    int half = d & 31;
    float c = cosp[t * 32 + half];
    float s = sinp[t * 32 + half];

    const float* row = g_qkv + (size_t)t * NQKV + (size_t)(g * (H_ + 2)) * D_;

#pragma unroll 4
    for (int h = 0; h < H_; h++) {
        const float* x = row + h * D_;
        float v0 = x[d], out;
        if (d < 32) { float v1 = x[d + 32]; out = v0 * c - v1 * s; }
        else        { float v1 = x[d - 32]; out = v0 * c + v1 * s; }
        g_q[(((size_t)t * G_ + g) * H_ + h) * D_ + d] = out;
    }
    {
        const float* x = row + H_ * D_;
        float v0 = x[d], out;
        if (d < 32) { float v1 = x[d + 32]; out = v0 * c - v1 * s; }
        else        { float v1 = x[d - 32]; out = v0 * c + v1 * s; }
        g_k[((size_t)t * G_ + g) * D_ + d] = out;
    }
    g_v[((size_t)t * G_ + g) * D_ + d] = row[(H_ + 1) * D_ + d];
}

// ---------------------------------------------------------------------------
// Cache copy + scatter
// ---------------------------------------------------------------------------
__global__ void cache_copy(const float* __restrict__ src, float* __restrict__ dst)
{
    size_t i = (size_t)blockIdx.x * blockDim.x + threadIdx.x;
    const float4* s4 = (const float4*)src;
    float4* d4 = (float4*)dst;
    size_t n4 = CACHE_ELEMS / 4;
    for (; i < n4; i += (size_t)gridDim.x * blockDim.x) d4[i] = s4[i];
}

__global__ void cache_scatter(const int* __restrict__ slots, float* __restrict__ dst)
{
    int t = blockIdx.x;
    int g = blockIdx.y;
    int d = threadIdx.x;
    int slot = slots[t];
    size_t kidx = ((size_t)slot * G_ + g) * D_ + d;
    dst[kidx] = g_k[((size_t)t * G_ + g) * D_ + d];
    dst[(size_t)CACHE_SLOTS * G_ * D_ + kidx] = g_v[((size_t)t * G_ + g) * D_ + d];
}

// ---------------------------------------------------------------------------
// Flash attention (causal, fp32, packed f32x2 math):
// one query row per thread, online softmax, keys processed 2 at a time.
// ---------------------------------------------------------------------------
__global__ __launch_bounds__(256) void attn_kernel()
{
    int task = blockIdx.x;
    int h = task % H_;
    int g = (task / H_) % G_;
    int b = task / (H_ * G_);
    int qi = blockIdx.y * 256 + threadIdx.x;
    int t  = b * S_ + qi;

    u64 q2[32], acc2[32];
    {
        const u64* qrow = (const u64*)(g_q + (((size_t)t * G_ + g) * H_ + h) * D_);
#pragma unroll
        for (int i = 0; i < 32; i++) q2[i] = qrow[i];
    }
#pragma unroll
    for (int i = 0; i < 32; i++) acc2[i] = 0ULL;

    float m = -INFINITY, l = 0.f;

    __shared__ __align__(16) float Ks[64][D_];
    __shared__ __align__(16) float Vs[64][D_];

    int kv_end = (blockIdx.y + 1) * 256;

    for (int t0 = 0; t0 < kv_end; t0 += 64) {
        __syncthreads();
        for (int i = threadIdx.x; i < 64 * D_ / 4; i += 256) {
            int j = i >> 4, d = (i & 15) * 4;
            size_t src = ((size_t)(b * S_ + t0 + j) * G_ + g) * D_ + d;
            *(float4*)&Ks[j][d] = *(const float4*)(g_k + src);
            *(float4*)&Vs[j][d] = *(const float4*)(g_v + src);
        }
        __syncthreads();

        int jmax = qi - t0 + 1;
        if (jmax > 64) jmax = 64;
        for (int j = 0; j < jmax; j += 2) {
            const bool v1ok = (j + 1 < jmax);
            const u64* k0 = (const u64*)Ks[j];
            const u64* k1 = (const u64*)Ks[j + 1];
            // two independent scores, 4 partial accumulators each
            u64 sa0 = 0, sb0 = 0, sc0 = 0, sd0 = 0;
            u64 sa1 = 0, sb1 = 0, sc1 = 0, sd1 = 0;
#pragma unroll
            for (int i = 0; i < 8; i++) {
                sa0 = fma2(q2[4 * i + 0], k0[4 * i + 0], sa0);
                sb0 = fma2(q2[4 * i + 1], k0[4 * i + 1], sb0);
                sc0 = fma2(q2[4 * i + 2], k0[4 * i + 2], sc0);
                sd0 = fma2(q2[4 * i + 3], k0[4 * i + 3], sd0);
                sa1 = fma2(q2[4 * i + 0], k1[4 * i + 0], sa1);
                sb1 = fma2(q2[4 * i + 1], k1[4 * i + 1], sb1);
                sc1 = fma2(q2[4 * i + 2], k1[4 * i + 2], sc1);
                sd1 = fma2(q2[4 * i + 3], k1[4 * i + 3], sd1);
            }
            u64 s20 = add2(add2(sa0, sb0), add2(sc0, sd0));
            u64 s21 = add2(add2(sa1, sb1), add2(sc1, sd1));
            float x0, y0, x1, y1;
            unpack2(s20, x0, y0);
            unpack2(s21, x1, y1);
            float s0 = (x0 + y0) * SCALE_;
            float s1 = v1ok ? (x1 + y1) * SCALE_ : -1e30f;

            float mx = fmaxf(m, fmaxf(s0, s1));
            if (mx > m) {
                float corr = __expf(m - mx);
                l *= corr;
                u64 c2 = pack2(corr, corr);
#pragma unroll
                for (int i = 0; i < 32; i++) acc2[i] = mul2(acc2[i], c2);
                m = mx;
            }
            float p0 = __expf(s0 - m);
            float p1 = __expf(s1 - m);
            l += p0 + p1;
            u64 p20 = pack2(p0, p0);
            u64 p21 = pack2(p1, p1);
            const u64* v0 = (const u64*)Vs[j];
            const u64* v1 = (const u64*)Vs[j + 1];
#pragma unroll
            for (int i = 0; i < 32; i++) {
                acc2[i] = fma2(p20, v0[i], acc2[i]);
                acc2[i] = fma2(p21, v1[i], acc2[i]);
            }
        }
    }

    float inv = 1.f / l;
    u64 inv2 = pack2(inv, inv);
    u64* orow = (u64*)(g_attn + (size_t)t * HID_ + (size_t)(g * H_ + h) * D_);
#pragma unroll
    for (int i = 0; i < 32; i++) orow[i] = mul2(acc2[i], inv2);
}

// ---------------------------------------------------------------------------
// kernel_launch
// ---------------------------------------------------------------------------
extern "C" void kernel_launch(void* const* d_in, const int* in_sizes, int n_in,
                              void* d_out, int out_size)
{
    const float* hidden  = (const float*)d_in[0];
    const float* cosp    = (const float*)d_in[1];
    const float* sinp    = (const float*)d_in[2];
    const float* w_qkv   = (const float*)d_in[3];
    const float* b_qkv   = (const float*)d_in[4];
    const float* w_dense = (const float*)d_in[5];
    const float* b_dense = (const float*)d_in[6];
    const float* kvcache = (const float*)d_in[7];
    const int*   slots   = (const int*)d_in[8];

    float* out       = (float*)d_out;
    float* out_cache = out + OUT_ELEMS;

    float *p_qkv, *p_attn;
    cudaGetSymbolAddress((void**)&p_qkv, g_qkv);
    cudaGetSymbolAddress((void**)&p_attn, g_attn);

    cudaFuncSetAttribute(gemm_tf32mma,
        cudaFuncAttributeMaxDynamicSharedMemorySize, GEMM_SMEM);

    // 1) QKV GEMM (tf32 HMMA): [2048,8192] @ [8192,9216] + b_qkv
    gemm_tf32mma<<<dim3(T_ / BM, NQKV / BN), 256, GEMM_SMEM>>>(
        hidden, w_qkv, b_qkv, p_qkv, HID_, NQKV);

    // 2) rotary + split
    rotary_split<<<dim3(T_, G_), 64>>>(cosp, sinp);

    // 3) cache
    cache_copy<<<4096, 256>>>(kvcache, out_cache);
    cache_scatter<<<dim3(T_, G_), 64>>>(slots, out_cache);

    // 4) attention (f32x2)
    attn_kernel<<<dim3(B_ * G_ * H_, S_ / 256), 256>>>();

    // 5) dense GEMM (tf32 HMMA): [2048,8192] @ [8192,8192] + b_dense
    gemm_tf32mma<<<dim3(T_ / BM, HID_ / BN), 256, GEMM_SMEM>>>(
        p_attn, w_dense, b_dense, out, HID_, HID_);
}

// round 5
// speedup vs baseline: 4.0339x; 1.8233x over previous
#include <cuda_runtime.h>
#include <cuda_fp16.h>
#include <math.h>
#include <stdint.h>

// Problem constants (FlashRWLargeAttention_59064390255025)
#define G_   8
#define H_   16
#define D_   64
#define B_   2
#define S_   1024
#define T_   (B_ * S_)            // 2048
#define HID_ (G_ * H_ * D_)       // 8192
#define NQKV (G_ * (H_ + 2) * D_) // 9216
#define CACHE_SLOTS 4096
#define CACHE_ELEMS (2 * CACHE_SLOTS * G_ * D_)
#define OUT_ELEMS ((size_t)T_ * HID_)
#define SCALE_ 0.125f

typedef unsigned long long u64;

// Scratch (__device__ globals; no allocs allowed)
__device__ float  g_qkv   [(size_t)T_ * NQKV];     // QKV GEMM out (f32)
__device__ float  g_q     [(size_t)T_ * HID_];     // rotated Q (f32)
__device__ float  g_k     [(size_t)T_ * G_ * D_];
__device__ float  g_v     [(size_t)T_ * G_ * D_];
__device__ __half g_hid_h [(size_t)T_ * HID_];     // hidden in half
__device__ __half g_attn_h[(size_t)T_ * HID_];     // attention out in half
__device__ __half g_wqkv_t[(size_t)NQKV * HID_];   // w_qkv  transposed [N][K] half
__device__ __half g_wdns_t[(size_t)HID_ * HID_];   // w_dense transposed [N][K] half

// ---------------------------------------------------------------------------
// helpers
// ---------------------------------------------------------------------------
__device__ __forceinline__ uint32_t smem_u32(const void* p) {
    uint32_t r;
    asm("{ .reg .u64 t; cvta.to.shared.u64 t, %1; cvt.u32.u64 %0, t; }"
        : "=r"(r) : "l"(p));
    return r;
}
__device__ __forceinline__ void cp16(uint32_t dst, const void* src) {
    asm volatile("cp.async.cg.shared.global [%0], [%1], 16;"
                 :: "r"(dst), "l"(src) : "memory");
}
// packed f32x2 helpers
__device__ __forceinline__ u64 fma2(u64 a, u64 b, u64 c) {
    u64 d; asm("fma.rn.f32x2 %0, %1, %2, %3;" : "=l"(d) : "l"(a), "l"(b), "l"(c));
    return d;
}
__device__ __forceinline__ u64 add2(u64 a, u64 b) {
    u64 d; asm("add.rn.f32x2 %0, %1, %2;" : "=l"(d) : "l"(a), "l"(b));
    return d;
}
__device__ __forceinline__ u64 mul2(u64 a, u64 b) {
    u64 d; asm("mul.rn.f32x2 %0, %1, %2;" : "=l"(d) : "l"(a), "l"(b));
    return d;
}
__device__ __forceinline__ u64 pack2(float lo, float hi) {
    u64 r; asm("mov.b64 %0, {%1, %2};" : "=l"(r) : "f"(lo), "f"(hi));
    return r;
}
__device__ __forceinline__ void unpack2(u64 v, float& lo, float& hi) {
    asm("mov.b64 {%0, %1}, %2;" : "=f"(lo), "=f"(hi) : "l"(v));
}

// ---------------------------------------------------------------------------
// Pre-convert kernels
// ---------------------------------------------------------------------------
// Wt[n][k] = half(W[k][n]) — 32x32 smem tile transpose
__global__ __launch_bounds__(256) void cvt_transpose(
    const float* __restrict__ W, __half* __restrict__ Wt, int K, int N)
{
    __shared__ float s[32][33];
    int n0 = blockIdx.x * 32, k0 = blockIdx.y * 32;
    int x = threadIdx.x & 31, y = threadIdx.x >> 5;  // x 0..31, y 0..7
#pragma unroll
    for (int i = 0; i < 4; i++)
        s[y + 8 * i][x] = W[(size_t)(k0 + y + 8 * i) * N + n0 + x];
    __syncthreads();
#pragma unroll
    for (int i = 0; i < 4; i++)
        Wt[(size_t)(n0 + y + 8 * i) * K + k0 + x] = __float2half(s[x][y + 8 * i]);
}

// elementwise f32 -> half
__global__ __launch_bounds__(256) void cvt_half(
    const float* __restrict__ src, __half* __restrict__ dst, size_t n4)
{
    size_t i = (size_t)blockIdx.x * blockDim.x + threadIdx.x;
    for (; i < n4; i += (size_t)gridDim.x * blockDim.x) {
        float4 v = ((const float4*)src)[i];
        __half2 h0 = __floats2half2_rn(v.x, v.y);
        __half2 h1 = __floats2half2_rn(v.z, v.w);
        uint2 o = { *(uint32_t*)&h0, *(uint32_t*)&h1 };
        ((uint2*)dst)[i] = o;
    }
}

// ---------------------------------------------------------------------------
// fp16 mma.sync GEMM: C[M,N](f32) = A[M,K](half) @ Wt[N,K](half)^T + bias
// CTA 128x256x32, 8 warps (2m x 4n), warp tile 64x64. HMMA m16n8k16.
// 4-stage cp.async pipeline. SMEM rows padded to 40 halves (80B) ->
// conflict-free fragment reads (bank = r*20+c mod 32 all distinct per 8r x 4c).
// ---------------------------------------------------------------------------
#define BM 128
#define BN 256
#define BK 32
#define RPAD 40                        // halves per smem row
#define A_BYTES (BM * RPAD * 2)        // 10240
#define B_BYTES (BN * RPAD * 2)        // 20480
#define STG_BYTES (A_BYTES + B_BYTES)  // 30720
#define NSTG 4
#define GEMM_SMEM (NSTG * STG_BYTES)   // 122880

__device__ __forceinline__ void mma_f16(float* c, const uint32_t* a,
                                        const uint32_t* b) {
    asm volatile(
        "mma.sync.aligned.m16n8k16.row.col.f32.f16.f16.f32 "
        "{%0,%1,%2,%3}, {%4,%5,%6,%7}, {%8,%9}, {%0,%1,%2,%3};\n"
        : "+f"(c[0]), "+f"(c[1]), "+f"(c[2]), "+f"(c[3])
        : "r"(a[0]), "r"(a[1]), "r"(a[2]), "r"(a[3]), "r"(b[0]), "r"(b[1]));
}

__global__ __launch_bounds__(256, 1) void gemm_f16(
    const __half* __restrict__ A, const __half* __restrict__ Wt,
    const float* __restrict__ bias, float* __restrict__ C,
    int K, int N)
{
    extern __shared__ __align__(16) uint8_t smem[];
    const uint32_t sbase = smem_u32(smem);
    const int tid = threadIdx.x;
    const int wid = tid >> 5, lane = tid & 31;
    const int l4r = lane >> 2, l4c = lane & 3;
    const int wm = (wid >> 2) * 64;
    const int wn = (wid & 3) * 64;
    const int row0 = blockIdx.x * BM;
    const int col0 = blockIdx.y * BN;

    float acc[4][8][4];
#pragma unroll
    for (int mi = 0; mi < 4; mi++)
#pragma unroll
        for (int ni = 0; ni < 8; ni++)
#pragma unroll
            for (int j = 0; j < 4; j++) acc[mi][ni][j] = 0.f;

    const int NT = K / BK;

    // per-thread loader coords (A: 2 chunks, B: 4 chunks of 16B)
    const int am[2] = { (tid * 2) >> 3, (tid * 2 + 1) >> 3 };       // wrong helper; compute inline below

    // issue stage
    auto issue = [&](int kt) {
        const int st = kt & (NSTG - 1);
        const uint32_t sA = sbase + st * STG_BYTES;
        const uint32_t sB = sA + A_BYTES;
        const int k0 = kt * BK;
#pragma unroll
        for (int i = 0; i < 2; i++) {
            int idx = i * 256 + tid;          // 0..511
            int m = idx >> 2, c = idx & 3;
            cp16(sA + (uint32_t)(m * 80 + c * 16),
                 A + (size_t)(row0 + m) * K + k0 + c * 8);
        }
#pragma unroll
        for (int i = 0; i < 4; i++) {
            int idx = i * 256 + tid;          // 0..1023
            int n = idx >> 2, c = idx & 3;
            cp16(sB + (uint32_t)(n * 80 + c * 16),
                 Wt + (size_t)(col0 + n) * K + k0 + c * 8);
        }
        asm volatile("cp.async.commit_group;" ::: "memory");
    };
    (void)am;

    issue(0); issue(1); issue(2);

    for (int kt = 0; kt < NT; kt++) {
        if (kt + 3 < NT) {
            issue(kt + 3);
            asm volatile("cp.async.wait_group 3;" ::: "memory");
        } else {
            asm volatile("cp.async.wait_group 0;" ::: "memory");
        }
        __syncthreads();

        const int st = kt & (NSTG - 1);
        const uint32_t* As = (const uint32_t*)(smem + st * STG_BYTES);
        const uint32_t* Bs = (const uint32_t*)(smem + st * STG_BYTES + A_BYTES);

#pragma unroll
        for (int ks = 0; ks < 2; ks++) {
            const int kw = ks * 8;   // word offset (16 halves)
            uint32_t af[4][4];
#pragma unroll
            for (int mi = 0; mi < 4; mi++) {
                int r = wm + mi * 16 + l4r;
                af[mi][0] = As[r * 20 + kw + l4c];
                af[mi][1] = As[(r + 8) * 20 + kw + l4c];
                af[mi][2] = As[r * 20 + kw + l4c + 4];
                af[mi][3] = As[(r + 8) * 20 + kw + l4c + 4];
            }
            uint32_t bf[8][2];
#pragma unroll
            for (int ni = 0; ni < 8; ni++) {
                int n = wn + ni * 8 + l4r;
                bf[ni][0] = Bs[n * 20 + kw + l4c];
                bf[ni][1] = Bs[n * 20 + kw + l4c + 4];
            }
#pragma unroll
            for (int mi = 0; mi < 4; mi++)
#pragma unroll
                for (int ni = 0; ni < 8; ni++)
                    mma_f16(acc[mi][ni], af[mi], bf[ni]);
        }
        __syncthreads();
    }

    // epilogue: C = acc + bias
#pragma unroll
    for (int mi = 0; mi < 4; mi++) {
        int r = row0 + wm + mi * 16 + l4r;
#pragma unroll
        for (int ni = 0; ni < 8; ni++) {
            int c = col0 + wn + ni * 8 + l4c * 2;
            float b0 = bias[c], b1 = bias[c + 1];
            float2 v0 = { acc[mi][ni][0] + b0, acc[mi][ni][1] + b1 };
            float2 v1 = { acc[mi][ni][2] + b0, acc[mi][ni][3] + b1 };
            *(float2*)(C + (size_t)r * N + c) = v0;
            *(float2*)(C + (size_t)(r + 8) * N + c) = v1;
        }
    }
}

// ---------------------------------------------------------------------------
// Rotary + split + cache scatter fused
// ---------------------------------------------------------------------------
__global__ void rotary_split(const float* __restrict__ cosp,
                             const float* __restrict__ sinp,
                             const int* __restrict__ slots,
                             float* __restrict__ cache_dst)
{
    int t = blockIdx.x;
    int g = blockIdx.y;
    int d = threadIdx.x;
    int half = d & 31;
    float c = cosp[t * 32 + half];
    float s = sinp[t * 32 + half];

    const float* row = g_qkv + (size_t)t * NQKV + (size_t)(g * (H_ + 2)) * D_;

#pragma unroll 4
    for (int h = 0; h < H_; h++) {
        const float* x = row + h * D_;
        float v0 = x[d], out;
        if (d < 32) { float v1 = x[d + 32]; out = v0 * c - v1 * s; }
        else        { float v1 = x[d - 32]; out = v0 * c + v1 * s; }
        g_q[(((size_t)t * G_ + g) * H_ + h) * D_ + d] = out;
    }
    float kv_k, kv_v;
    {
        const float* x = row + H_ * D_;
        float v0 = x[d];
        if (d < 32) { float v1 = x[d + 32]; kv_k = v0 * c - v1 * s; }
        else        { float v1 = x[d - 32]; kv_k = v0 * c + v1 * s; }
        g_k[((size_t)t * G_ + g) * D_ + d] = kv_k;
    }
    kv_v = row[(H_ + 1) * D_ + d];
    g_v[((size_t)t * G_ + g) * D_ + d] = kv_v;

    // scatter into cache output
    int slot = slots[t];
    size_t kidx = ((size_t)slot * G_ + g) * D_ + d;
    cache_dst[kidx] = kv_k;
    cache_dst[(size_t)CACHE_SLOTS * G_ * D_ + kidx] = kv_v;
}

// ---------------------------------------------------------------------------
// Cache copy
// ---------------------------------------------------------------------------
__global__ void cache_copy(const float* __restrict__ src, float* __restrict__ dst)
{
    size_t i = (size_t)blockIdx.x * blockDim.x + threadIdx.x;
    const float4* s4 = (const float4*)src;
    float4* d4 = (float4*)dst;
    size_t n4 = CACHE_ELEMS / 4;
    for (; i < n4; i += (size_t)gridDim.x * blockDim.x) d4[i] = s4[i];
}

// ---------------------------------------------------------------------------
// Flash attention (causal, fp32 f32x2 math), writes half output
// ---------------------------------------------------------------------------
__global__ __launch_bounds__(256) void attn_kernel()
{
    int task = blockIdx.x;
    int h = task % H_;
    int g = (task / H_) % G_;
    int b = task / (H_ * G_);
    int qi = blockIdx.y * 256 + threadIdx.x;
    int t  = b * S_ + qi;

    u64 q2[32], acc2[32];
    {
        const u64* qrow = (const u64*)(g_q + (((size_t)t * G_ + g) * H_ + h) * D_);
#pragma unroll
        for (int i = 0; i < 32; i++) q2[i] = qrow[i];
    }
#pragma unroll
    for (int i = 0; i < 32; i++) acc2[i] = 0ULL;

    float m = -INFINITY, l = 0.f;

    __shared__ __align__(16) float Ks[64][D_];
    __shared__ __align__(16) float Vs[64][D_];

    int kv_end = (blockIdx.y + 1) * 256;

    for (int t0 = 0; t0 < kv_end; t0 += 64) {
        __syncthreads();
        for (int i = threadIdx.x; i < 64 * D_ / 4; i += 256) {
            int j = i >> 4, d = (i & 15) * 4;
            size_t src = ((size_t)(b * S_ + t0 + j) * G_ + g) * D_ + d;
            *(float4*)&Ks[j][d] = *(const float4*)(g_k + src);
            *(float4*)&Vs[j][d] = *(const float4*)(g_v + src);
        }
        __syncthreads();

        int jmax = qi - t0 + 1;
        if (jmax > 64) jmax = 64;
        for (int j = 0; j < jmax; j += 2) {
            const bool v1ok = (j + 1 < jmax);
            const u64* k0 = (const u64*)Ks[j];
            const u64* k1 = (const u64*)Ks[j + 1];
            u64 sa0 = 0, sb0 = 0, sc0 = 0, sd0 = 0;
            u64 sa1 = 0, sb1 = 0, sc1 = 0, sd1 = 0;
#pragma unroll
            for (int i = 0; i < 8; i++) {
                sa0 = fma2(q2[4 * i + 0], k0[4 * i + 0], sa0);
                sb0 = fma2(q2[4 * i + 1], k0[4 * i + 1], sb0);
                sc0 = fma2(q2[4 * i + 2], k0[4 * i + 2], sc0);
                sd0 = fma2(q2[4 * i + 3], k0[4 * i + 3], sd0);
                sa1 = fma2(q2[4 * i + 0], k1[4 * i + 0], sa1);
                sb1 = fma2(q2[4 * i + 1], k1[4 * i + 1], sb1);
                sc1 = fma2(q2[4 * i + 2], k1[4 * i + 2], sc1);
                sd1 = fma2(q2[4 * i + 3], k1[4 * i + 3], sd1);
            }
            u64 s20 = add2(add2(sa0, sb0), add2(sc0, sd0));
            u64 s21 = add2(add2(sa1, sb1), add2(sc1, sd1));
            float x0, y0, x1, y1;
            unpack2(s20, x0, y0);
            unpack2(s21, x1, y1);
            float s0 = (x0 + y0) * SCALE_;
            float s1 = v1ok ? (x1 + y1) * SCALE_ : -1e30f;

            float mx = fmaxf(m, fmaxf(s0, s1));
            if (mx > m) {
                float corr = __expf(m - mx);
                l *= corr;
                u64 c2 = pack2(corr, corr);
#pragma unroll
                for (int i = 0; i < 32; i++) acc2[i] = mul2(acc2[i], c2);
                m = mx;
            }
            float p0 = __expf(s0 - m);
            float p1 = __expf(s1 - m);
            l += p0 + p1;
            u64 p20 = pack2(p0, p0);
            u64 p21 = pack2(p1, p1);
            const u64* v0 = (const u64*)Vs[j];
            const u64* v1 = (const u64*)Vs[j + 1];
#pragma unroll
            for (int i = 0; i < 32; i++) {
                acc2[i] = fma2(p20, v0[i], acc2[i]);
                acc2[i] = fma2(p21, v1[i], acc2[i]);
            }
        }
    }

    float inv = 1.f / l;
    __half2* orow = (__half2*)(g_attn_h + (size_t)t * HID_ + (size_t)(g * H_ + h) * D_);
#pragma unroll
    for (int i = 0; i < 32; i++) {
        float lo, hi;
        unpack2(acc2[i], lo, hi);
        orow[i] = __floats2half2_rn(lo * inv, hi * inv);
    }
}

// ---------------------------------------------------------------------------
// kernel_launch
// ---------------------------------------------------------------------------
extern "C" void kernel_launch(void* const* d_in, const int* in_sizes, int n_in,
                              void* d_out, int out_size)
{
    const float* hidden  = (const float*)d_in[0];
    const float* cosp    = (const float*)d_in[1];
    const float* sinp    = (const float*)d_in[2];
    const float* w_qkv   = (const float*)d_in[3];
    const float* b_qkv   = (const float*)d_in[4];
    const float* w_dense = (const float*)d_in[5];
    const float* b_dense = (const float*)d_in[6];
    const float* kvcache = (const float*)d_in[7];
    const int*   slots   = (const int*)d_in[8];

    float* out       = (float*)d_out;
    float* out_cache = out + OUT_ELEMS;

    float  *p_qkv;
    __half *p_hid, *p_attn, *p_wq, *p_wd;
    cudaGetSymbolAddress((void**)&p_qkv,  g_qkv);
    cudaGetSymbolAddress((void**)&p_hid,  g_hid_h);
    cudaGetSymbolAddress((void**)&p_attn, g_attn_h);
    cudaGetSymbolAddress((void**)&p_wq,   g_wqkv_t);
    cudaGetSymbolAddress((void**)&p_wd,   g_wdns_t);

    cudaFuncSetAttribute(gemm_f16,
        cudaFuncAttributeMaxDynamicSharedMemorySize, GEMM_SMEM);

    // 1-3) pre-convert: weights (transpose to [N][K] half), hidden -> half
    cvt_transpose<<<dim3(NQKV / 32, HID_ / 32), 256>>>(w_qkv, p_wq, HID_, NQKV);
    cvt_transpose<<<dim3(HID_ / 32, HID_ / 32), 256>>>(w_dense, p_wd, HID_, HID_);
    cvt_half<<<1024, 256>>>(hidden, p_hid, OUT_ELEMS / 4);

    // 4) QKV GEMM (fp16 HMMA): [2048,8192] @ [8192,9216] + b_qkv -> f32
    gemm_f16<<<dim3(T_ / BM, NQKV / BN), 256, GEMM_SMEM>>>(
        p_hid, p_wq, b_qkv, p_qkv, HID_, NQKV);

    // 5) cache background copy
    cache_copy<<<4096, 256>>>(kvcache, out_cache);

    // 6) rotary + split + cache scatter
    rotary_split<<<dim3(T_, G_), 64>>>(cosp, sinp, slots, out_cache);

    // 7) attention -> g_attn_h (half)
    attn_kernel<<<dim3(B_ * G_ * H_, S_ / 256), 256>>>();

    // 8) dense GEMM (fp16 HMMA): [2048,8192] @ [8192,8192] + b_dense
    gemm_f16<<<dim3(T_ / BM, HID_ / BN), 256, GEMM_SMEM>>>(
        p_attn, p_wd, b_dense, out, HID_, HID_);
}

// round 6
// speedup vs baseline: 8.7235x; 2.1625x over previous
#include <cuda_runtime.h>
#include <cuda_fp16.h>
#include <math.h>
#include <stdint.h>

// Problem constants (FlashRWLargeAttention_59064390255025)
#define G_   8
#define H_   16
#define D_   64
#define B_   2
#define S_   1024
#define T_   (B_ * S_)            // 2048
#define HID_ (G_ * H_ * D_)       // 8192
#define NQKV (G_ * (H_ + 2) * D_) // 9216
#define CACHE_SLOTS 4096
#define CACHE_ELEMS (2 * CACHE_SLOTS * G_ * D_)
#define OUT_ELEMS ((size_t)T_ * HID_)
#define SCALE_ 0.125f

// Scratch (__device__ globals; no allocs allowed)
__device__ float  g_qkv   [(size_t)T_ * NQKV];     // QKV GEMM out (f32)
__device__ __half g_qh    [(size_t)T_ * HID_];     // rotated Q (half, pre-scaled)
__device__ __half g_kh    [(size_t)T_ * G_ * D_];  // rotated K (half)
__device__ __half g_vh    [(size_t)T_ * G_ * D_];  // V (half)
__device__ __half g_hid_h [(size_t)T_ * HID_];     // hidden in half
__device__ __half g_attn_h[(size_t)T_ * HID_];     // attention out (half)
__device__ __half g_wqkv_t[(size_t)NQKV * HID_];   // w_qkv^T  [N][K] half
__device__ __half g_wdns_t[(size_t)HID_ * HID_];   // w_dense^T [N][K] half

// ---------------------------------------------------------------------------
// helpers
// ---------------------------------------------------------------------------
__device__ __forceinline__ uint32_t smem_u32(const void* p) {
    uint32_t r;
    asm("{ .reg .u64 t; cvta.to.shared.u64 t, %1; cvt.u32.u64 %0, t; }"
        : "=r"(r) : "l"(p));
    return r;
}
__device__ __forceinline__ void cp16(uint32_t dst, const void* src) {
    asm volatile("cp.async.cg.shared.global [%0], [%1], 16;"
                 :: "r"(dst), "l"(src) : "memory");
}
__device__ __forceinline__ void ldm_x4(uint32_t* r, uint32_t addr) {
    asm volatile("ldmatrix.sync.aligned.m8n8.x4.shared.b16 {%0,%1,%2,%3}, [%4];"
                 : "=r"(r[0]), "=r"(r[1]), "=r"(r[2]), "=r"(r[3]) : "r"(addr));
}
__device__ __forceinline__ void ldm_x4t(uint32_t* r, uint32_t addr) {
    asm volatile("ldmatrix.sync.aligned.m8n8.x4.trans.shared.b16 {%0,%1,%2,%3}, [%4];"
                 : "=r"(r[0]), "=r"(r[1]), "=r"(r[2]), "=r"(r[3]) : "r"(addr));
}
__device__ __forceinline__ void mma_f16(float* c, const uint32_t* a,
                                        const uint32_t* b) {
    asm volatile(
        "mma.sync.aligned.m16n8k16.row.col.f32.f16.f16.f32 "
        "{%0,%1,%2,%3}, {%4,%5,%6,%7}, {%8,%9}, {%0,%1,%2,%3};\n"
        : "+f"(c[0]), "+f"(c[1]), "+f"(c[2]), "+f"(c[3])
        : "r"(a[0]), "r"(a[1]), "r"(a[2]), "r"(a[3]), "r"(b[0]), "r"(b[1]));
}
__device__ __forceinline__ uint32_t h2pack(float a, float b) {
    __half2 h = __floats2half2_rn(a, b);
    return *(uint32_t*)&h;
}

// ---------------------------------------------------------------------------
// Pre-convert kernels
// ---------------------------------------------------------------------------
__global__ __launch_bounds__(256) void cvt_transpose(
    const float* __restrict__ W, __half* __restrict__ Wt, int K, int N)
{
    __shared__ float s[32][33];
    int n0 = blockIdx.x * 32, k0 = blockIdx.y * 32;
    int x = threadIdx.x & 31, y = threadIdx.x >> 5;
#pragma unroll
    for (int i = 0; i < 4; i++)
        s[y + 8 * i][x] = W[(size_t)(k0 + y + 8 * i) * N + n0 + x];
    __syncthreads();
#pragma unroll
    for (int i = 0; i < 4; i++)
        Wt[(size_t)(n0 + y + 8 * i) * K + k0 + x] = __float2half(s[x][y + 8 * i]);
}

__global__ __launch_bounds__(256) void cvt_half(
    const float* __restrict__ src, __half* __restrict__ dst, size_t n4)
{
    size_t i = (size_t)blockIdx.x * blockDim.x + threadIdx.x;
    for (; i < n4; i += (size_t)gridDim.x * blockDim.x) {
        float4 v = ((const float4*)src)[i];
        __half2 h0 = __floats2half2_rn(v.x, v.y);
        __half2 h1 = __floats2half2_rn(v.z, v.w);
        uint2 o = { *(uint32_t*)&h0, *(uint32_t*)&h1 };
        ((uint2*)dst)[i] = o;
    }
}

// ---------------------------------------------------------------------------
// fp16 HMMA GEMM v3: C[M,N](f32) = A[M,K](half) @ Wt[N,K](half)^T + bias
// CTA 128x256x64, 8 warps (2m x 4n), warp tile 64x64. ldmatrix.x4 frags.
// 4-stage cp.async pipeline, issue AFTER compute (race-free, 1 barrier/tile).
// Rows padded to 72 halves (144B): ldmatrix conflict-free (16r mod 128).
// ---------------------------------------------------------------------------
#define BM 128
#define BN 256
#define BK 64
#define RPADB 144                      // bytes per smem row
#define A_BYTES (BM * RPADB)           // 18432
#define B_BYTES (BN * RPADB)           // 36864
#define STG_BYTES (A_BYTES + B_BYTES)  // 55296
#define NSTG 4
#define GEMM_SMEM (NSTG * STG_BYTES)   // 221184

__global__ __launch_bounds__(256, 1) void gemm_f16(
    const __half* __restrict__ A, const __half* __restrict__ Wt,
    const float* __restrict__ bias, float* __restrict__ C,
    int K, int N)
{
    extern __shared__ __align__(128) uint8_t smem[];
    const uint32_t sbase = smem_u32(smem);
    const int tid = threadIdx.x;
    const int wid = tid >> 5, lane = tid & 31;
    const int l4r = lane >> 2, l4c = lane & 3;
    const int wm = (wid >> 2) * 64;
    const int wn = (wid & 3) * 64;
    const int row0 = blockIdx.x * BM;
    const int col0 = blockIdx.y * BN;

    // ldmatrix lane offsets
    const uint32_t rowA = (lane & 7) + ((lane >> 3) & 1) * 8;
    const uint32_t colA = (lane >> 4) * 16;
    const uint32_t rowB = (lane & 7) + (lane >> 4) * 8;
    const uint32_t colB = ((lane >> 3) & 1) * 16;

    float acc[4][8][4];
#pragma unroll
    for (int mi = 0; mi < 4; mi++)
#pragma unroll
        for (int ni = 0; ni < 8; ni++)
#pragma unroll
            for (int j = 0; j < 4; j++) acc[mi][ni][j] = 0.f;

    const int NT = K / BK;   // 128

    auto issue = [&](int kt) {
        const int st = kt & (NSTG - 1);
        const uint32_t sA = sbase + st * STG_BYTES;
        const uint32_t sB = sA + A_BYTES;
        const int k0 = kt * BK;
#pragma unroll
        for (int i = 0; i < 4; i++) {
            int idx = i * 256 + tid;          // 0..1023
            int m = idx >> 3, c = idx & 7;
            cp16(sA + (uint32_t)(m * RPADB + c * 16),
                 A + (size_t)(row0 + m) * K + k0 + c * 8);
        }
#pragma unroll
        for (int i = 0; i < 8; i++) {
            int idx = i * 256 + tid;          // 0..2047
            int n = idx >> 3, c = idx & 7;
            cp16(sB + (uint32_t)(n * RPADB + c * 16),
                 Wt + (size_t)(col0 + n) * K + k0 + c * 8);
        }
        asm volatile("cp.async.commit_group;" ::: "memory");
    };

    issue(0); issue(1); issue(2);

    for (int kt = 0; kt < NT; kt++) {
        const int rem = NT - 1 - kt;
        if (rem >= 2)      asm volatile("cp.async.wait_group 2;" ::: "memory");
        else if (rem == 1) asm volatile("cp.async.wait_group 1;" ::: "memory");
        else               asm volatile("cp.async.wait_group 0;" ::: "memory");
        __syncthreads();

        const int st = kt & (NSTG - 1);
        const uint32_t sA = sbase + st * STG_BYTES;
        const uint32_t sB = sA + A_BYTES;

#pragma unroll
        for (int ks = 0; ks < 4; ks++) {
            uint32_t af[4][4];
#pragma unroll
            for (int mi = 0; mi < 4; mi++)
                ldm_x4(af[mi], sA + (wm + mi * 16 + rowA) * RPADB + ks * 32 + colA);
            uint32_t bf[8][2];
#pragma unroll
            for (int nip = 0; nip < 4; nip++) {
                uint32_t r[4];
                ldm_x4(r, sB + (wn + nip * 16 + rowB) * RPADB + ks * 32 + colB);
                bf[2 * nip][0] = r[0]; bf[2 * nip][1] = r[1];
                bf[2 * nip + 1][0] = r[2]; bf[2 * nip + 1][1] = r[3];
            }
#pragma unroll
            for (int mi = 0; mi < 4; mi++)
#pragma unroll
                for (int ni = 0; ni < 8; ni++)
                    mma_f16(acc[mi][ni], af[mi], bf[ni]);
        }
        if (kt + 3 < NT) issue(kt + 3);
    }

    // epilogue
#pragma unroll
    for (int mi = 0; mi < 4; mi++) {
        int r = row0 + wm + mi * 16 + l4r;
#pragma unroll
        for (int ni = 0; ni < 8; ni++) {
            int c = col0 + wn + ni * 8 + l4c * 2;
            float b0 = bias[c], b1 = bias[c + 1];
            float2 v0 = { acc[mi][ni][0] + b0, acc[mi][ni][1] + b1 };
            float2 v1 = { acc[mi][ni][2] + b0, acc[mi][ni][3] + b1 };
            *(float2*)(C + (size_t)r * N + c) = v0;
            *(float2*)(C + (size_t)(r + 8) * N + c) = v1;
        }
    }
}

// ---------------------------------------------------------------------------
// Rotary + split + cache scatter; emits half Q (pre-scaled by 0.125), K, V
// ---------------------------------------------------------------------------
__global__ void rotary_split(const float* __restrict__ cosp,
                             const float* __restrict__ sinp,
                             const int* __restrict__ slots,
                             float* __restrict__ cache_dst)
{
    int t = blockIdx.x;
    int g = blockIdx.y;
    int d = threadIdx.x;
    int half = d & 31;
    float c = cosp[t * 32 + half];
    float s = sinp[t * 32 + half];

    const float* row = g_qkv + (size_t)t * NQKV + (size_t)(g * (H_ + 2)) * D_;

#pragma unroll 4
    for (int h = 0; h < H_; h++) {
        const float* x = row + h * D_;
        float v0 = x[d], out;
        if (d < 32) { float v1 = x[d + 32]; out = v0 * c - v1 * s; }
        else        { float v1 = x[d - 32]; out = v0 * c + v1 * s; }
        g_qh[(size_t)t * HID_ + (size_t)(g * H_ + h) * D_ + d] =
            __float2half(out * SCALE_);
    }
    float kv_k, kv_v;
    {
        const float* x = row + H_ * D_;
        float v0 = x[d];
        if (d < 32) { float v1 = x[d + 32]; kv_k = v0 * c - v1 * s; }
        else        { float v1 = x[d - 32]; kv_k = v0 * c + v1 * s; }
    }
    kv_v = row[(H_ + 1) * D_ + d];
    g_kh[((size_t)t * G_ + g) * D_ + d] = __float2half(kv_k);
    g_vh[((size_t)t * G_ + g) * D_ + d] = __float2half(kv_v);

    int slot = slots[t];
    size_t kidx = ((size_t)slot * G_ + g) * D_ + d;
    cache_dst[kidx] = kv_k;
    cache_dst[(size_t)CACHE_SLOTS * G_ * D_ + kidx] = kv_v;
}

__global__ void cache_copy(const float* __restrict__ src, float* __restrict__ dst)
{
    size_t i = (size_t)blockIdx.x * blockDim.x + threadIdx.x;
    const float4* s4 = (const float4*)src;
    float4* d4 = (float4*)dst;
    size_t n4 = CACHE_ELEMS / 4;
    for (; i < n4; i += (size_t)gridDim.x * blockDim.x) d4[i] = s4[i];
}

// ---------------------------------------------------------------------------
// Flash attention v2 with HMMA. Grid (B*G*H, S/64), 128 threads (4 warps).
// Each warp: 16 query rows. K tiles of 64 keys in smem (padded 144B rows).
// Scores m16n8k16 (k=d), online softmax in accumulator layout, P stays in
// registers as the A-fragment for P@V (ldmatrix.x4.trans on V).
// ---------------------------------------------------------------------------
#define ATT_RPAD 144
__global__ __launch_bounds__(128) void attn_fa()
{
    __shared__ __align__(128) uint8_t asm_[2 * 64 * ATT_RPAD];
    const uint32_t sK = smem_u32(asm_);
    const uint32_t sV = sK + 64 * ATT_RPAD;

    const int task = blockIdx.x;
    const int h = task % H_;
    const int g = (task / H_) % G_;
    const int b = task / (H_ * G_);
    const int qt0 = blockIdx.y * 64;
    const int tid = threadIdx.x, wid = tid >> 5, lane = tid & 31;
    const int qw0 = qt0 + wid * 16;
    const int l4r = lane >> 2, l4c = lane & 3;

    // ldmatrix lane offsets (same derivations as GEMM)
    const uint32_t rowB = (lane & 7) + (lane >> 4) * 8;          // K frags
    const uint32_t colB = ((lane >> 3) & 1) * 16;
    const uint32_t rowV = (lane & 7) + ((lane >> 3) & 1) * 8;    // V frags (trans)
    const uint32_t colV = (lane >> 4) * 16;

    // Q fragments: qa[kc][0..3], kc = d-chunk of 16
    uint32_t qa[4][4];
    {
        const __half* qA = g_qh + (size_t)(b * S_ + qw0 + l4r) * HID_
                         + (size_t)(g * H_ + h) * D_;
        const __half* qB = qA + (size_t)8 * HID_;
#pragma unroll
        for (int kc = 0; kc < 4; kc++) {
            qa[kc][0] = *(const uint32_t*)(qA + kc * 16 + 2 * l4c);
            qa[kc][1] = *(const uint32_t*)(qB + kc * 16 + 2 * l4c);
            qa[kc][2] = *(const uint32_t*)(qA + kc * 16 + 8 + 2 * l4c);
            qa[kc][3] = *(const uint32_t*)(qB + kc * 16 + 8 + 2 * l4c);
        }
    }

    float o[8][4];
#pragma unroll
    for (int ni = 0; ni < 8; ni++)
#pragma unroll
        for (int e = 0; e < 4; e++) o[ni][e] = 0.f;
    float m0 = -INFINITY, m1 = -INFINITY, l0 = 0.f, l1 = 0.f;

    const int ntile = qt0 / 64 + 1;
    for (int jt = 0; jt < ntile; jt++) {
        const int j0 = jt * 64;
        // cooperative K/V tile load
#pragma unroll
        for (int i = 0; i < 4; i++) {
            int idx = i * 128 + tid;      // 0..511
            int j = idx >> 3, c = idx & 7;
            size_t src = ((size_t)(b * S_ + j0 + j) * G_ + g) * D_ + c * 8;
            cp16(sK + j * ATT_RPAD + c * 16, g_kh + src);
            cp16(sV + j * ATT_RPAD + c * 16, g_vh + src);
        }
        asm volatile("cp.async.commit_group;" ::: "memory");
        asm volatile("cp.async.wait_group 0;" ::: "memory");
        __syncthreads();

        if (j0 <= qw0 + 15) {
            // ---- scores S = Q @ K^T (pre-scaled) ----
            float s[8][4];
#pragma unroll
            for (int ni = 0; ni < 8; ni++)
#pragma unroll
                for (int e = 0; e < 4; e++) s[ni][e] = 0.f;
#pragma unroll
            for (int kc = 0; kc < 4; kc++) {
                uint32_t bk[8][2];
#pragma unroll
                for (int nip = 0; nip < 4; nip++) {
                    uint32_t r[4];
                    ldm_x4(r, sK + (nip * 16 + rowB) * ATT_RPAD + kc * 32 + colB);
                    bk[2 * nip][0] = r[0]; bk[2 * nip][1] = r[1];
                    bk[2 * nip + 1][0] = r[2]; bk[2 * nip + 1][1] = r[3];
                }
#pragma unroll
                for (int ni = 0; ni < 8; ni++)
                    mma_f16(s[ni], qa[kc], bk[ni]);
            }
            // ---- causal mask (diagonal tiles only) ----
            if (j0 + 63 > qw0) {
                const int rq0 = qw0 + l4r, rq1 = rq0 + 8;
#pragma unroll
                for (int ni = 0; ni < 8; ni++) {
                    int k0i = j0 + ni * 8 + 2 * l4c;
                    if (k0i > rq0)     s[ni][0] = -1e30f;
                    if (k0i + 1 > rq0) s[ni][1] = -1e30f;
                    if (k0i > rq1)     s[ni][2] = -1e30f;
                    if (k0i + 1 > rq1) s[ni][3] = -1e30f;
                }
            }
            // ---- online softmax ----
            float mx0 = -1e30f, mx1 = -1e30f;
#pragma unroll
            for (int ni = 0; ni < 8; ni++) {
                mx0 = fmaxf(mx0, fmaxf(s[ni][0], s[ni][1]));
                mx1 = fmaxf(mx1, fmaxf(s[ni][2], s[ni][3]));
            }
            mx0 = fmaxf(mx0, __shfl_xor_sync(0xffffffffu, mx0, 1));
            mx0 = fmaxf(mx0, __shfl_xor_sync(0xffffffffu, mx0, 2));
            mx1 = fmaxf(mx1, __shfl_xor_sync(0xffffffffu, mx1, 1));
            mx1 = fmaxf(mx1, __shfl_xor_sync(0xffffffffu, mx1, 2));
            float m0n = fmaxf(m0, mx0), m1n = fmaxf(m1, mx1);
            float sum0 = 0.f, sum1 = 0.f;
#pragma unroll
            for (int ni = 0; ni < 8; ni++) {
                s[ni][0] = __expf(s[ni][0] - m0n);
                s[ni][1] = __expf(s[ni][1] - m0n);
                s[ni][2] = __expf(s[ni][2] - m1n);
                s[ni][3] = __expf(s[ni][3] - m1n);
                sum0 += s[ni][0] + s[ni][1];
                sum1 += s[ni][2] + s[ni][3];
            }
            sum0 += __shfl_xor_sync(0xffffffffu, sum0, 1);
            sum0 += __shfl_xor_sync(0xffffffffu, sum0, 2);
            sum1 += __shfl_xor_sync(0xffffffffu, sum1, 1);
            sum1 += __shfl_xor_sync(0xffffffffu, sum1, 2);
            float c0 = __expf(m0 - m0n), c1 = __expf(m1 - m1n);
            l0 = l0 * c0 + sum0;
            l1 = l1 * c1 + sum1;
            m0 = m0n; m1 = m1n;
#pragma unroll
            for (int ni = 0; ni < 8; ni++) {
                o[ni][0] *= c0; o[ni][1] *= c0;
                o[ni][2] *= c1; o[ni][3] *= c1;
            }
            // ---- P (half) as A-fragment, P @ V ----
            uint32_t ph[4][4];
#pragma unroll
            for (int kc = 0; kc < 4; kc++) {
                ph[kc][0] = h2pack(s[2 * kc][0], s[2 * kc][1]);
                ph[kc][1] = h2pack(s[2 * kc][2], s[2 * kc][3]);
                ph[kc][2] = h2pack(s[2 * kc + 1][0], s[2 * kc + 1][1]);
                ph[kc][3] = h2pack(s[2 * kc + 1][2], s[2 * kc + 1][3]);
            }
#pragma unroll
            for (int kc = 0; kc < 4; kc++) {
                uint32_t bv[8][2];
#pragma unroll
                for (int nip = 0; nip < 4; nip++) {
                    uint32_t r[4];
                    ldm_x4t(r, sV + (kc * 16 + rowV) * ATT_RPAD + nip * 32 + colV);
                    bv[2 * nip][0] = r[0]; bv[2 * nip][1] = r[1];
                    bv[2 * nip + 1][0] = r[2]; bv[2 * nip + 1][1] = r[3];
                }
#pragma unroll
                for (int ni = 0; ni < 8; ni++)
                    mma_f16(o[ni], ph[kc], bv[ni]);
            }
        }
        __syncthreads();
    }

    // ---- write O (half) ----
    float inv0 = 1.f / l0, inv1 = 1.f / l1;
    {
        __half* oA = g_attn_h + (size_t)(b * S_ + qw0 + l4r) * HID_
                   + (size_t)(g * H_ + h) * D_ + 2 * l4c;
        __half* oB = oA + (size_t)8 * HID_;
#pragma unroll
        for (int ni = 0; ni < 8; ni++) {
            uint32_t hA = h2pack(o[ni][0] * inv0, o[ni][1] * inv0);
            uint32_t hB = h2pack(o[ni][2] * inv1, o[ni][3] * inv1);
            *(uint32_t*)(oA + ni * 8) = hA;
            *(uint32_t*)(oB + ni * 8) = hB;
        }
    }
}

// ---------------------------------------------------------------------------
// kernel_launch
// ---------------------------------------------------------------------------
extern "C" void kernel_launch(void* const* d_in, const int* in_sizes, int n_in,
                              void* d_out, int out_size)
{
    const float* hidden  = (const float*)d_in[0];
    const float* cosp    = (const float*)d_in[1];
    const float* sinp    = (const float*)d_in[2];
    const float* w_qkv   = (const float*)d_in[3];
    const float* b_qkv   = (const float*)d_in[4];
    const float* w_dense = (const float*)d_in[5];
    const float* b_dense = (const float*)d_in[6];
    const float* kvcache = (const float*)d_in[7];
    const int*   slots   = (const int*)d_in[8];

    float* out       = (float*)d_out;
    float* out_cache = out + OUT_ELEMS;

    float  *p_qkv;
    __half *p_hid, *p_attn, *p_wq, *p_wd;
    cudaGetSymbolAddress((void**)&p_qkv,  g_qkv);
    cudaGetSymbolAddress((void**)&p_hid,  g_hid_h);
    cudaGetSymbolAddress((void**)&p_attn, g_attn_h);
    cudaGetSymbolAddress((void**)&p_wq,   g_wqkv_t);
    cudaGetSymbolAddress((void**)&p_wd,   g_wdns_t);

    cudaFuncSetAttribute(gemm_f16,
        cudaFuncAttributeMaxDynamicSharedMemorySize, GEMM_SMEM);

    // 1-3) pre-convert
    cvt_transpose<<<dim3(NQKV / 32, HID_ / 32), 256>>>(w_qkv, p_wq, HID_, NQKV);
    cvt_transpose<<<dim3(HID_ / 32, HID_ / 32), 256>>>(w_dense, p_wd, HID_, HID_);
    cvt_half<<<1024, 256>>>(hidden, p_hid, OUT_ELEMS / 4);

    // 4) QKV GEMM
    gemm_f16<<<dim3(T_ / BM, NQKV / BN), 256, GEMM_SMEM>>>(
        p_hid, p_wq, b_qkv, p_qkv, HID_, NQKV);

    // 5) cache background copy
    cache_copy<<<4096, 256>>>(kvcache, out_cache);

    // 6) rotary + split (half QKV) + cache scatter
    rotary_split<<<dim3(T_, G_), 64>>>(cosp, sinp, slots, out_cache);

    // 7) flash attention (HMMA)
    attn_fa<<<dim3(B_ * G_ * H_, S_ / 64), 128>>>();

    // 8) dense GEMM
    gemm_f16<<<dim3(T_ / BM, HID_ / BN), 256, GEMM_SMEM>>>(
        p_attn, p_wd, b_dense, out, HID_, HID_);
}

// round 7
// speedup vs baseline: 9.1894x; 1.0534x over previous
#include <cuda_runtime.h>
#include <cuda_fp16.h>
#include <math.h>
#include <stdint.h>

// Problem constants (FlashRWLargeAttention_59064390255025)
#define G_   8
#define H_   16
#define D_   64
#define B_   2
#define S_   1024
#define T_   (B_ * S_)            // 2048
#define HID_ (G_ * H_ * D_)       // 8192
#define NQKV (G_ * (H_ + 2) * D_) // 9216
#define CACHE_SLOTS 4096
#define CACHE_ELEMS (2 * CACHE_SLOTS * G_ * D_)
#define OUT_ELEMS ((size_t)T_ * HID_)
#define SCALE_ 0.125f

// Scratch (__device__ globals; no allocs allowed)
__device__ float  g_qkv   [(size_t)T_ * NQKV];     // QKV GEMM out (f32)
__device__ __half g_qh    [(size_t)T_ * HID_];     // rotated Q (half, pre-scaled)
__device__ __half g_kh    [(size_t)T_ * G_ * D_];  // rotated K (half)
__device__ __half g_vh    [(size_t)T_ * G_ * D_];  // V (half)
__device__ __half g_hid_h [(size_t)T_ * HID_];     // hidden in half
__device__ __half g_attn_h[(size_t)T_ * HID_];     // attention out (half)
__device__ __half g_wqkv_t[(size_t)NQKV * HID_];   // w_qkv^T  [N][K] half
__device__ __half g_wdns_t[(size_t)HID_ * HID_];   // w_dense^T [N][K] half

// ---------------------------------------------------------------------------
// helpers
// ---------------------------------------------------------------------------
__device__ __forceinline__ uint32_t smem_u32(const void* p) {
    uint32_t r;
    asm("{ .reg .u64 t; cvta.to.shared.u64 t, %1; cvt.u32.u64 %0, t; }"
        : "=r"(r) : "l"(p));
    return r;
}
__device__ __forceinline__ void cp16(uint32_t dst, const void* src) {
    asm volatile("cp.async.cg.shared.global [%0], [%1], 16;"
                 :: "r"(dst), "l"(src) : "memory");
}
__device__ __forceinline__ void ldm_x4(uint32_t* r, uint32_t addr) {
    asm volatile("ldmatrix.sync.aligned.m8n8.x4.shared.b16 {%0,%1,%2,%3}, [%4];"
                 : "=r"(r[0]), "=r"(r[1]), "=r"(r[2]), "=r"(r[3]) : "r"(addr));
}
__device__ __forceinline__ void ldm_x4t(uint32_t* r, uint32_t addr) {
    asm volatile("ldmatrix.sync.aligned.m8n8.x4.trans.shared.b16 {%0,%1,%2,%3}, [%4];"
                 : "=r"(r[0]), "=r"(r[1]), "=r"(r[2]), "=r"(r[3]) : "r"(addr));
}
__device__ __forceinline__ void mma_f16(float* c, const uint32_t* a,
                                        const uint32_t* b) {
    asm volatile(
        "mma.sync.aligned.m16n8k16.row.col.f32.f16.f16.f32 "
        "{%0,%1,%2,%3}, {%4,%5,%6,%7}, {%8,%9}, {%0,%1,%2,%3};\n"
        : "+f"(c[0]), "+f"(c[1]), "+f"(c[2]), "+f"(c[3])
        : "r"(a[0]), "r"(a[1]), "r"(a[2]), "r"(a[3]), "r"(b[0]), "r"(b[1]));
}
__device__ __forceinline__ uint32_t h2pack(float a, float b) {
    __half2 h = __floats2half2_rn(a, b);
    return *(uint32_t*)&h;
}

// ---------------------------------------------------------------------------
// Pre-convert kernels
// ---------------------------------------------------------------------------
__global__ __launch_bounds__(256) void cvt_transpose(
    const float* __restrict__ W, __half* __restrict__ Wt, int K, int N)
{
    __shared__ float s[32][33];
    int n0 = blockIdx.x * 32, k0 = blockIdx.y * 32;
    int x = threadIdx.x & 31, y = threadIdx.x >> 5;
#pragma unroll
    for (int i = 0; i < 4; i++)
        s[y + 8 * i][x] = W[(size_t)(k0 + y + 8 * i) * N + n0 + x];
    __syncthreads();
#pragma unroll
    for (int i = 0; i < 4; i++)
        Wt[(size_t)(n0 + y + 8 * i) * K + k0 + x] = __float2half(s[x][y + 8 * i]);
}

__global__ __launch_bounds__(256) void cvt_half(
    const float* __restrict__ src, __half* __restrict__ dst, size_t n4)
{
    size_t i = (size_t)blockIdx.x * blockDim.x + threadIdx.x;
    for (; i < n4; i += (size_t)gridDim.x * blockDim.x) {
        float4 v = ((const float4*)src)[i];
        __half2 h0 = __floats2half2_rn(v.x, v.y);
        __half2 h1 = __floats2half2_rn(v.z, v.w);
        uint2 o = { *(uint32_t*)&h0, *(uint32_t*)&h1 };
        ((uint2*)dst)[i] = o;
    }
}

// ---------------------------------------------------------------------------
// fp16 HMMA GEMM v4: C[M,N](f32) = A[M,K](half) @ Wt[N,K](half)^T + bias
// CTA 128x128x64, 8 warps (2m x 4n), warp tile 64x32. 2 CTAs/SM.
// 3-stage cp.async pipeline, issue after compute (race-free).
// ---------------------------------------------------------------------------
#define BM 128
#define BN 128
#define BK 64
#define RPADB 144                      // bytes per smem row (64 halves + pad)
#define A_BYTES (BM * RPADB)           // 18432
#define B_BYTES (BN * RPADB)           // 18432
#define STG_BYTES (A_BYTES + B_BYTES)  // 36864
#define NSTG 3
#define GEMM_SMEM (NSTG * STG_BYTES)   // 110592

__global__ __launch_bounds__(256, 2) void gemm_f16(
    const __half* __restrict__ A, const __half* __restrict__ Wt,
    const float* __restrict__ bias, float* __restrict__ C,
    int K, int N)
{
    extern __shared__ __align__(128) uint8_t smem[];
    const uint32_t sbase = smem_u32(smem);
    const int tid = threadIdx.x;
    const int wid = tid >> 5, lane = tid & 31;
    const int l4r = lane >> 2, l4c = lane & 3;
    const int wm = (wid >> 2) * 64;    // 0 / 64
    const int wn = (wid & 3) * 32;     // 0/32/64/96
    const int row0 = blockIdx.x * BM;
    const int col0 = blockIdx.y * BN;

    // ldmatrix lane offsets
    const uint32_t rowA = (lane & 7) + ((lane >> 3) & 1) * 8;
    const uint32_t colA = (lane >> 4) * 16;
    const uint32_t rowB = (lane & 7) + (lane >> 4) * 8;
    const uint32_t colB = ((lane >> 3) & 1) * 16;

    float acc[4][4][4];
#pragma unroll
    for (int mi = 0; mi < 4; mi++)
#pragma unroll
        for (int ni = 0; ni < 4; ni++)
#pragma unroll
            for (int j = 0; j < 4; j++) acc[mi][ni][j] = 0.f;

    const int NT = K / BK;   // 128

    auto issue = [&](int kt) {
        const int st = kt % NSTG;
        const uint32_t sA = sbase + st * STG_BYTES;
        const uint32_t sB = sA + A_BYTES;
        const int k0 = kt * BK;
#pragma unroll
        for (int i = 0; i < 4; i++) {
            int idx = i * 256 + tid;          // 0..1023
            int m = idx >> 3, c = idx & 7;
            cp16(sA + (uint32_t)(m * RPADB + c * 16),
                 A + (size_t)(row0 + m) * K + k0 + c * 8);
        }
#pragma unroll
        for (int i = 0; i < 4; i++) {
            int idx = i * 256 + tid;          // 0..1023
            int n = idx >> 3, c = idx & 7;
            cp16(sB + (uint32_t)(n * RPADB + c * 16),
                 Wt + (size_t)(col0 + n) * K + k0 + c * 8);
        }
        asm volatile("cp.async.commit_group;" ::: "memory");
    };

    issue(0); issue(1);

    for (int kt = 0; kt < NT; kt++) {
        if (kt + 1 < NT) asm volatile("cp.async.wait_group 1;" ::: "memory");
        else             asm volatile("cp.async.wait_group 0;" ::: "memory");
        __syncthreads();

        const int st = kt % NSTG;
        const uint32_t sA = sbase + st * STG_BYTES;
        const uint32_t sB = sA + A_BYTES;

#pragma unroll
        for (int ks = 0; ks < 4; ks++) {
            uint32_t af[4][4];
#pragma unroll
            for (int mi = 0; mi < 4; mi++)
                ldm_x4(af[mi], sA + (wm + mi * 16 + rowA) * RPADB + ks * 32 + colA);
            uint32_t bf[4][2];
#pragma unroll
            for (int nip = 0; nip < 2; nip++) {
                uint32_t r[4];
                ldm_x4(r, sB + (wn + nip * 16 + rowB) * RPADB + ks * 32 + colB);
                bf[2 * nip][0] = r[0]; bf[2 * nip][1] = r[1];
                bf[2 * nip + 1][0] = r[2]; bf[2 * nip + 1][1] = r[3];
            }
#pragma unroll
            for (int mi = 0; mi < 4; mi++)
#pragma unroll
                for (int ni = 0; ni < 4; ni++)
                    mma_f16(acc[mi][ni], af[mi], bf[ni]);
        }
        if (kt + 2 < NT) issue(kt + 2);
    }

    // epilogue
#pragma unroll
    for (int mi = 0; mi < 4; mi++) {
        int r = row0 + wm + mi * 16 + l4r;
#pragma unroll
        for (int ni = 0; ni < 4; ni++) {
            int c = col0 + wn + ni * 8 + l4c * 2;
            float b0 = bias[c], b1 = bias[c + 1];
            float2 v0 = { acc[mi][ni][0] + b0, acc[mi][ni][1] + b1 };
            float2 v1 = { acc[mi][ni][2] + b0, acc[mi][ni][3] + b1 };
            *(float2*)(C + (size_t)r * N + c) = v0;
            *(float2*)(C + (size_t)(r + 8) * N + c) = v1;
        }
    }
}

// ---------------------------------------------------------------------------
// Rotary + split + cache scatter; emits half Q (pre-scaled by 0.125), K, V
// ---------------------------------------------------------------------------
__global__ void rotary_split(const float* __restrict__ cosp,
                             const float* __restrict__ sinp,
                             const int* __restrict__ slots,
                             float* __restrict__ cache_dst)
{
    int t = blockIdx.x;
    int g = blockIdx.y;
    int d = threadIdx.x;
    int half = d & 31;
    float c = cosp[t * 32 + half];
    float s = sinp[t * 32 + half];

    const float* row = g_qkv + (size_t)t * NQKV + (size_t)(g * (H_ + 2)) * D_;

#pragma unroll 4
    for (int h = 0; h < H_; h++) {
        const float* x = row + h * D_;
        float v0 = x[d], out;
        if (d < 32) { float v1 = x[d + 32]; out = v0 * c - v1 * s; }
        else        { float v1 = x[d - 32]; out = v0 * c + v1 * s; }
        g_qh[(size_t)t * HID_ + (size_t)(g * H_ + h) * D_ + d] =
            __float2half(out * SCALE_);
    }
    float kv_k, kv_v;
    {
        const float* x = row + H_ * D_;
        float v0 = x[d];
        if (d < 32) { float v1 = x[d + 32]; kv_k = v0 * c - v1 * s; }
        else        { float v1 = x[d - 32]; kv_k = v0 * c + v1 * s; }
    }
    kv_v = row[(H_ + 1) * D_ + d];
    g_kh[((size_t)t * G_ + g) * D_ + d] = __float2half(kv_k);
    g_vh[((size_t)t * G_ + g) * D_ + d] = __float2half(kv_v);

    int slot = slots[t];
    size_t kidx = ((size_t)slot * G_ + g) * D_ + d;
    cache_dst[kidx] = kv_k;
    cache_dst[(size_t)CACHE_SLOTS * G_ * D_ + kidx] = kv_v;
}

__global__ void cache_copy(const float* __restrict__ src, float* __restrict__ dst)
{
    size_t i = (size_t)blockIdx.x * blockDim.x + threadIdx.x;
    const float4* s4 = (const float4*)src;
    float4* d4 = (float4*)dst;
    size_t n4 = CACHE_ELEMS / 4;
    for (; i < n4; i += (size_t)gridDim.x * blockDim.x) d4[i] = s4[i];
}

// ---------------------------------------------------------------------------
// Flash attention v2 with HMMA. Grid (B*G*H, S/64), 128 threads (4 warps).
// ---------------------------------------------------------------------------
#define ATT_RPAD 144
__global__ __launch_bounds__(128) void attn_fa()
{
    __shared__ __align__(128) uint8_t asm_[2 * 64 * ATT_RPAD];
    const uint32_t sK = smem_u32(asm_);
    const uint32_t sV = sK + 64 * ATT_RPAD;

    const int task = blockIdx.x;
    const int h = task % H_;
    const int g = (task / H_) % G_;
    const int b = task / (H_ * G_);
    const int qt0 = blockIdx.y * 64;
    const int tid = threadIdx.x, wid = tid >> 5, lane = tid & 31;
    const int qw0 = qt0 + wid * 16;
    const int l4r = lane >> 2, l4c = lane & 3;

    const uint32_t rowB = (lane & 7) + (lane >> 4) * 8;          // K frags
    const uint32_t colB = ((lane >> 3) & 1) * 16;
    const uint32_t rowV = (lane & 7) + ((lane >> 3) & 1) * 8;    // V frags (trans)
    const uint32_t colV = (lane >> 4) * 16;

    uint32_t qa[4][4];
    {
        const __half* qA = g_qh + (size_t)(b * S_ + qw0 + l4r) * HID_
                         + (size_t)(g * H_ + h) * D_;
        const __half* qB = qA + (size_t)8 * HID_;
#pragma unroll
        for (int kc = 0; kc < 4; kc++) {
            qa[kc][0] = *(const uint32_t*)(qA + kc * 16 + 2 * l4c);
            qa[kc][1] = *(const uint32_t*)(qB + kc * 16 + 2 * l4c);
            qa[kc][2] = *(const uint32_t*)(qA + kc * 16 + 8 + 2 * l4c);
            qa[kc][3] = *(const uint32_t*)(qB + kc * 16 + 8 + 2 * l4c);
        }
    }

    float o[8][4];
#pragma unroll
    for (int ni = 0; ni < 8; ni++)
#pragma unroll
        for (int e = 0; e < 4; e++) o[ni][e] = 0.f;
    float m0 = -INFINITY, m1 = -INFINITY, l0 = 0.f, l1 = 0.f;

    const int ntile = qt0 / 64 + 1;
    for (int jt = 0; jt < ntile; jt++) {
        const int j0 = jt * 64;
#pragma unroll
        for (int i = 0; i < 4; i++) {
            int idx = i * 128 + tid;
            int j = idx >> 3, c = idx & 7;
            size_t src = ((size_t)(b * S_ + j0 + j) * G_ + g) * D_ + c * 8;
            cp16(sK + j * ATT_RPAD + c * 16, g_kh + src);
            cp16(sV + j * ATT_RPAD + c * 16, g_vh + src);
        }
        asm volatile("cp.async.commit_group;" ::: "memory");
        asm volatile("cp.async.wait_group 0;" ::: "memory");
        __syncthreads();

        if (j0 <= qw0 + 15) {
            float s[8][4];
#pragma unroll
            for (int ni = 0; ni < 8; ni++)
#pragma unroll
                for (int e = 0; e < 4; e++) s[ni][e] = 0.f;
#pragma unroll
            for (int kc = 0; kc < 4; kc++) {
                uint32_t bk[8][2];
#pragma unroll
                for (int nip = 0; nip < 4; nip++) {
                    uint32_t r[4];
                    ldm_x4(r, sK + (nip * 16 + rowB) * ATT_RPAD + kc * 32 + colB);
                    bk[2 * nip][0] = r[0]; bk[2 * nip][1] = r[1];
                    bk[2 * nip + 1][0] = r[2]; bk[2 * nip + 1][1] = r[3];
                }
#pragma unroll
                for (int ni = 0; ni < 8; ni++)
                    mma_f16(s[ni], qa[kc], bk[ni]);
            }
            if (j0 + 63 > qw0) {
                const int rq0 = qw0 + l4r, rq1 = rq0 + 8;
#pragma unroll
                for (int ni = 0; ni < 8; ni++) {
                    int k0i = j0 + ni * 8 + 2 * l4c;
                    if (k0i > rq0)     s[ni][0] = -1e30f;
                    if (k0i + 1 > rq0) s[ni][1] = -1e30f;
                    if (k0i > rq1)     s[ni][2] = -1e30f;
                    if (k0i + 1 > rq1) s[ni][3] = -1e30f;
                }
            }
            float mx0 = -1e30f, mx1 = -1e30f;
#pragma unroll
            for (int ni = 0; ni < 8; ni++) {
                mx0 = fmaxf(mx0, fmaxf(s[ni][0], s[ni][1]));
                mx1 = fmaxf(mx1, fmaxf(s[ni][2], s[ni][3]));
            }
            mx0 = fmaxf(mx0, __shfl_xor_sync(0xffffffffu, mx0, 1));
            mx0 = fmaxf(mx0, __shfl_xor_sync(0xffffffffu, mx0, 2));
            mx1 = fmaxf(mx1, __shfl_xor_sync(0xffffffffu, mx1, 1));
            mx1 = fmaxf(mx1, __shfl_xor_sync(0xffffffffu, mx1, 2));
            float m0n = fmaxf(m0, mx0), m1n = fmaxf(m1, mx1);
            float sum0 = 0.f, sum1 = 0.f;
#pragma unroll
            for (int ni = 0; ni < 8; ni++) {
                s[ni][0] = __expf(s[ni][0] - m0n);
                s[ni][1] = __expf(s[ni][1] - m0n);
                s[ni][2] = __expf(s[ni][2] - m1n);
                s[ni][3] = __expf(s[ni][3] - m1n);
                sum0 += s[ni][0] + s[ni][1];
                sum1 += s[ni][2] + s[ni][3];
            }
            sum0 += __shfl_xor_sync(0xffffffffu, sum0, 1);
            sum0 += __shfl_xor_sync(0xffffffffu, sum0, 2);
            sum1 += __shfl_xor_sync(0xffffffffu, sum1, 1);
            sum1 += __shfl_xor_sync(0xffffffffu, sum1, 2);
            float c0 = __expf(m0 - m0n), c1 = __expf(m1 - m1n);
            l0 = l0 * c0 + sum0;
            l1 = l1 * c1 + sum1;
            m0 = m0n; m1 = m1n;
#pragma unroll
            for (int ni = 0; ni < 8; ni++) {
                o[ni][0] *= c0; o[ni][1] *= c0;
                o[ni][2] *= c1; o[ni][3] *= c1;
            }
            uint32_t ph[4][4];
#pragma unroll
            for (int kc = 0; kc < 4; kc++) {
                ph[kc][0] = h2pack(s[2 * kc][0], s[2 * kc][1]);
                ph[kc][1] = h2pack(s[2 * kc][2], s[2 * kc][3]);
                ph[kc][2] = h2pack(s[2 * kc + 1][0], s[2 * kc + 1][1]);
                ph[kc][3] = h2pack(s[2 * kc + 1][2], s[2 * kc + 1][3]);
            }
#pragma unroll
            for (int kc = 0; kc < 4; kc++) {
                uint32_t bv[8][2];
#pragma unroll
                for (int nip = 0; nip < 4; nip++) {
                    uint32_t r[4];
                    ldm_x4t(r, sV + (kc * 16 + rowV) * ATT_RPAD + nip * 32 + colV);
                    bv[2 * nip][0] = r[0]; bv[2 * nip][1] = r[1];
                    bv[2 * nip + 1][0] = r[2]; bv[2 * nip + 1][1] = r[3];
                }
#pragma unroll
                for (int ni = 0; ni < 8; ni++)
                    mma_f16(o[ni], ph[kc], bv[ni]);
            }
        }
        __syncthreads();
    }

    float inv0 = 1.f / l0, inv1 = 1.f / l1;
    {
        __half* oA = g_attn_h + (size_t)(b * S_ + qw0 + l4r) * HID_
                   + (size_t)(g * H_ + h) * D_ + 2 * l4c;
        __half* oB = oA + (size_t)8 * HID_;
#pragma unroll
        for (int ni = 0; ni < 8; ni++) {
            uint32_t hA = h2pack(o[ni][0] * inv0, o[ni][1] * inv0);
            uint32_t hB = h2pack(o[ni][2] * inv1, o[ni][3] * inv1);
            *(uint32_t*)(oA + ni * 8) = hA;
            *(uint32_t*)(oB + ni * 8) = hB;
        }
    }
}

// ---------------------------------------------------------------------------
// kernel_launch
// ---------------------------------------------------------------------------
extern "C" void kernel_launch(void* const* d_in, const int* in_sizes, int n_in,
                              void* d_out, int out_size)
{
    const float* hidden  = (const float*)d_in[0];
    const float* cosp    = (const float*)d_in[1];
    const float* sinp    = (const float*)d_in[2];
    const float* w_qkv   = (const float*)d_in[3];
    const float* b_qkv   = (const float*)d_in[4];
    const float* w_dense = (const float*)d_in[5];
    const float* b_dense = (const float*)d_in[6];
    const float* kvcache = (const float*)d_in[7];
    const int*   slots   = (const int*)d_in[8];

    float* out       = (float*)d_out;
    float* out_cache = out + OUT_ELEMS;

    float  *p_qkv;
    __half *p_hid, *p_attn, *p_wq, *p_wd;
    cudaGetSymbolAddress((void**)&p_qkv,  g_qkv);
    cudaGetSymbolAddress((void**)&p_hid,  g_hid_h);
    cudaGetSymbolAddress((void**)&p_attn, g_attn_h);
    cudaGetSymbolAddress((void**)&p_wq,   g_wqkv_t);
    cudaGetSymbolAddress((void**)&p_wd,   g_wdns_t);

    cudaFuncSetAttribute(gemm_f16,
        cudaFuncAttributeMaxDynamicSharedMemorySize, GEMM_SMEM);

    // 1-3) pre-convert
    cvt_transpose<<<dim3(NQKV / 32, HID_ / 32), 256>>>(w_qkv, p_wq, HID_, NQKV);
    cvt_transpose<<<dim3(HID_ / 32, HID_ / 32), 256>>>(w_dense, p_wd, HID_, HID_);
    cvt_half<<<1024, 256>>>(hidden, p_hid, OUT_ELEMS / 4);

    // 4) QKV GEMM
    gemm_f16<<<dim3(T_ / BM, NQKV / BN), 256, GEMM_SMEM>>>(
        p_hid, p_wq, b_qkv, p_qkv, HID_, NQKV);

    // 5) cache background copy
    cache_copy<<<4096, 256>>>(kvcache, out_cache);

    // 6) rotary + split (half QKV) + cache scatter
    rotary_split<<<dim3(T_, G_), 64>>>(cosp, sinp, slots, out_cache);

    // 7) flash attention (HMMA)
    attn_fa<<<dim3(B_ * G_ * H_, S_ / 64), 128>>>();

    // 8) dense GEMM
    gemm_f16<<<dim3(T_ / BM, HID_ / BN), 256, GEMM_SMEM>>>(
        p_attn, p_wd, b_dense, out, HID_, HID_);
}